// round 14
// baseline (speedup 1.0000x reference)
#include <cuda_runtime.h>
#include <cuda_fp16.h>
#include <math.h>
#include <stdint.h>

#define BQ 1024
#define TT 64
#define INDIM 64
#define LL 8
#define HHD 512
#define G4 2048
#define CC 128
#define NBLK 128

// ---------------- device scratch ----------------
__device__ __align__(128) __half g_P16[(size_t)TT * BQ * G4];      // gate preactivations fp16, permuted cols
__device__ __align__(128) __half g_H16[2][(size_t)TT * BQ * HHD];  // hidden seq fp16, ping-pong
__device__ __align__(128) __half g_X16[(size_t)TT * BQ * INDIM];   // x as fp16
__device__ __align__(128) uint32_t g_WiH[((size_t)INDIM + (LL - 1) * HHD) * G4 / 2]; // Wi fragments
__device__ __align__(128) uint32_t g_WrH[(size_t)LL * HHD * G4 / 2];                 // Wr fragments
__device__ __align__(128) uint32_t g_FcH[(size_t)TT * HHD * CC / 2];                 // fc_w fragments per t
__device__ float g_bias[LL * G4];
__device__ float g_fcp[(size_t)TT * BQ * CC];  // FC split-K partials
__device__ int g_bar_count;
__device__ volatile int g_phase;

__device__ __forceinline__ float sigm(float x) { return __fdividef(1.f, 1.f + __expf(-x)); }
__device__ __forceinline__ float tnh(float x) {
    float e = __expf(2.f * x);
    return 1.f - __fdividef(2.f, e + 1.f);
}

__device__ __forceinline__ void cp16(void* dst, const void* src) {
    uint32_t d = (uint32_t)__cvta_generic_to_shared(dst);
    asm volatile("cp.async.cg.shared.global [%0], [%1], 16;" ::"r"(d), "l"(src));
}

__device__ __forceinline__ void mma16(float* c, const uint32_t* a, uint32_t b0, uint32_t b1) {
    asm volatile(
        "mma.sync.aligned.m16n8k16.row.col.f32.f16.f16.f32 "
        "{%0,%1,%2,%3}, {%4,%5,%6,%7}, {%8,%9}, {%0,%1,%2,%3};"
        : "+f"(c[0]), "+f"(c[1]), "+f"(c[2]), "+f"(c[3])
        : "r"(a[0]), "r"(a[1]), "r"(a[2]), "r"(a[3]), "r"(b0), "r"(b1));
}

__device__ __forceinline__ void ldmat4(uint32_t* a, uint32_t addr) {
    asm volatile(
        "ldmatrix.sync.aligned.m8n8.x4.shared.b16 {%0,%1,%2,%3}, [%4];"
        : "=r"(a[0]), "=r"(a[1]), "=r"(a[2]), "=r"(a[3]) : "r"(addr));
}

#define CPCOMMIT() asm volatile("cp.async.commit_group;" ::: "memory")
#define CPWAIT(n) asm volatile("cp.async.wait_group %0;" ::"n"(n) : "memory")

// column permutation: n_log(g, j) = (j>>5)*128 + ((j>>3)&3)*32 + g*8 + (j&7)

// ---------------- weight prep: fp16 fragment images ----------------
__global__ void prep_wi(const float* __restrict__ w_ih0, const float* __restrict__ w_ih) {
    const size_t R0 = (size_t)INDIM * G4 / 2;
    size_t total = R0 + (size_t)(LL - 1) * HHD * G4 / 2;
    size_t stride = (size_t)gridDim.x * blockDim.x;
    for (size_t idx = (size_t)blockIdx.x * blockDim.x + threadIdx.x; idx < total; idx += stride) {
        int l;
        uint32_t rem;
        if (idx < R0) { l = 0; rem = (uint32_t)idx; }
        else { size_t r = idx - R0; l = 1 + (int)(r >> 19); rem = (uint32_t)(r & 524287u); }
        int rr = rem & 1, lane = (rem >> 1) & 31, n8 = (rem >> 6) & 255, k16 = rem >> 14;
        int k0 = k16 * 16 + (lane & 3) * 2 + rr * 8;
        int nlog = n8 * 8 + (lane >> 2);
        int j = ((nlog >> 7) << 5) + (((nlog >> 5) & 3) << 3) + (nlog & 7);
        int g = (nlog >> 3) & 3;
        float v0, v1;
        if (l == 0) {
            const float* p = w_ih0 + (size_t)(g * HHD + j) * INDIM + k0;
            v0 = p[0]; v1 = p[1];
        } else {
            const float* p = w_ih + ((size_t)(l - 1) * G4 + g * HHD + j) * HHD + k0;
            v0 = p[0]; v1 = p[1];
        }
        __half2 h = __floats2half2_rn(v0, v1);
        g_WiH[idx] = *(uint32_t*)&h;
    }
}

__global__ void prep_wr(const float* __restrict__ w_hh0, const float* __restrict__ w_hh) {
    size_t total = (size_t)LL * HHD * G4 / 2;
    size_t stride = (size_t)gridDim.x * blockDim.x;
    for (size_t idx = (size_t)blockIdx.x * blockDim.x + threadIdx.x; idx < total; idx += stride) {
        int l = (int)(idx >> 19);
        uint32_t rem = (uint32_t)(idx & 524287u);
        int rr = rem & 1, lane = (rem >> 1) & 31, n8 = (rem >> 6) & 255, k16 = rem >> 14;
        int k0 = k16 * 16 + (lane & 3) * 2 + rr * 8;
        int nlog = n8 * 8 + (lane >> 2);
        int j = ((nlog >> 7) << 5) + (((nlog >> 5) & 3) << 3) + (nlog & 7);
        int g = (nlog >> 3) & 3;
        float v0, v1;
        if (l == 0) {
            const float* p = w_hh0 + (size_t)(g * HHD + j) * HHD + k0;
            v0 = p[0]; v1 = p[1];
        } else {
            const float* p = w_hh + ((size_t)(l - 1) * G4 + g * HHD + j) * HHD + k0;
            v0 = p[0]; v1 = p[1];
        }
        __half2 h = __floats2half2_rn(v0, v1);
        g_WrH[idx] = *(uint32_t*)&h;
    }
}

// fc_w fragments: per t, [k16(32)][c8(16)][lane(32)][2]; value fc_w[c][t*HHD + k]
__global__ void prep_fcw(const float* __restrict__ fw) {
    size_t total = (size_t)TT * HHD * CC / 2;
    size_t stride = (size_t)gridDim.x * blockDim.x;
    for (size_t idx = (size_t)blockIdx.x * blockDim.x + threadIdx.x; idx < total; idx += stride) {
        uint32_t rem = (uint32_t)(idx & 32767u);
        int t = (int)(idx >> 15);
        int rr = rem & 1, lane = (rem >> 1) & 31, c8 = (rem >> 6) & 15, k16 = rem >> 10;
        int k0 = k16 * 16 + (lane & 3) * 2 + rr * 8;
        int c = c8 * 8 + (lane >> 2);
        const float* p = fw + (size_t)c * (TT * HHD) + (size_t)t * HHD + k0;
        __half2 h = __floats2half2_rn(p[0], p[1]);
        g_FcH[idx] = *(uint32_t*)&h;
    }
}

__global__ void prep_bias(const float* __restrict__ b_ih0, const float* __restrict__ b_hh0,
                          const float* __restrict__ b_ih, const float* __restrict__ b_hh) {
    int idx = blockIdx.x * blockDim.x + threadIdx.x;
    if (idx >= LL * G4) return;
    int l = idx >> 11, nlog = idx & 2047;
    int j = ((nlog >> 7) << 5) + (((nlog >> 5) & 3) << 3) + (nlog & 7);
    int g = (nlog >> 3) & 3;
    float v = (l == 0) ? (b_ih0[g * HHD + j] + b_hh0[g * HHD + j])
                       : (b_ih[(l - 1) * G4 + g * HHD + j] + b_hh[(l - 1) * G4 + g * HHD + j]);
    g_bias[idx] = v;
}

__global__ void prep_x(const float* __restrict__ x) {
    size_t total = (size_t)TT * BQ * INDIM;
    size_t stride = (size_t)gridDim.x * blockDim.x;
    for (size_t idx = (size_t)blockIdx.x * blockDim.x + threadIdx.x; idx < total; idx += stride) {
        int k = (int)(idx & 63);
        int r = (int)(idx >> 6);
        int b = r & (BQ - 1), t = r >> 10;
        g_X16[idx] = __float2half(x[((size_t)b * TT + t) * INDIM + k]);
    }
}

// proj/fc smem: sA[2][128*64 halves]=32768, sB[2][4096 u32]=32768
#define SB_OFF 32768
#define PROJ_SMEM 65536
// recur smem (K=128 chunks): sA[2][128*128 halves]=65536, sB[2][8192 u32]=65536 @65536,
// sP 128 x 136-half stride = 34816 @131072
#define RB_OFF 65536
#define RSP_OFF 131072
#define SP_STRIDE 136
#define RECUR_SMEM (RSP_OFF + 128 * SP_STRIDE * 2)

// ---------------- input projection: fp16 tensor GEMM (unchanged, R13 winner) ----------------
__global__ void __launch_bounds__(256, 2) proj16(int layer) {
    extern __shared__ char smem[];
    __half* sA = (__half*)smem;
    uint32_t* sB = (uint32_t*)(smem + SB_OFF);
    const uint32_t saddr = (uint32_t)__cvta_generic_to_shared(smem);

    const int tid = threadIdx.x, lane = tid & 31, wid = tid >> 5;
    const int warpM = wid >> 2, warpN = wid & 3;
    const int n8base = blockIdx.x * 16;
    const int n0 = blockIdx.x * 128;
    const int r0 = blockIdx.y * 128;
    const int K = (layer == 0) ? INDIM : HHD;
    const int NC = K / 64;
    const __half* __restrict__ A = (layer == 0) ? g_X16 : g_H16[(layer - 1) & 1];
    const uint32_t* __restrict__ W =
        g_WiH + ((layer == 0) ? (size_t)0 : (size_t)(INDIM * G4 / 2) + (size_t)(layer - 1) * (HHD * G4 / 2));

    const int quad = lane >> 3, rr8 = lane & 7;
    const int gsel = quad >> 1;
    const uint32_t abase = saddr + (uint32_t)(warpM * 64 + rr8 + (quad & 1) * 8) * 128;

    float acc[4][4][4];
#pragma unroll
    for (int mt = 0; mt < 4; mt++)
#pragma unroll
        for (int nt = 0; nt < 4; nt++)
#pragma unroll
            for (int q = 0; q < 4; q++) acc[mt][nt][q] = 0.f;

    auto load = [&](int kc, int s) {
        __half* sa = sA + s * 8192;
#pragma unroll
        for (int i = 0; i < 4; i++) {
            int u = i * 256 + tid;
            int row = u >> 3, seg = u & 7;
            cp16(sa + row * 64 + (seg ^ (row & 7)) * 8,
                 A + (size_t)(r0 + row) * K + kc * 64 + seg * 8);
        }
        uint32_t* sb = sB + s * 4096;
#pragma unroll
        for (int k16l = 0; k16l < 4; k16l++) {
            cp16(sb + k16l * 1024 + tid * 4,
                 W + ((size_t)(kc * 4 + k16l) * 256 + n8base) * 64 + tid * 4);
        }
        CPCOMMIT();
    };

    load(0, 0);
    if (NC > 1) load(1, 1);
    for (int kc = 0; kc < NC; kc++) {
        int s = kc & 1;
        if (kc + 2 <= NC) CPWAIT(1);
        else              CPWAIT(0);
        __syncthreads();
        const uint32_t sa_u = abase + s * 16384;
        const uint32_t* sb = sB + s * 4096;
#pragma unroll
        for (int k16l = 0; k16l < 4; k16l++) {
            const uint32_t grp = (uint32_t)(((k16l * 2 + gsel) ^ rr8) * 16);
            uint32_t a[4][4];
#pragma unroll
            for (int mt = 0; mt < 4; mt++) ldmat4(a[mt], sa_u + mt * 2048 + grp);
#pragma unroll
            for (int nt = 0; nt < 4; nt++) {
                uint2 b = *(const uint2*)(sb + (k16l * 16 + warpN * 4 + nt) * 64 + lane * 2);
#pragma unroll
                for (int mt = 0; mt < 4; mt++) mma16(acc[mt][nt], a[mt], b.x, b.y);
            }
        }
        __syncthreads();
        if (kc + 2 < NC) load(kc + 2, s);
    }

    const float* __restrict__ bias = g_bias + layer * G4;
#pragma unroll
    for (int nt = 0; nt < 4; nt++) {
        int ncol = n0 + warpN * 32 + nt * 8 + (lane & 3) * 2;
        float2 bv = *(const float2*)&bias[ncol];
#pragma unroll
        for (int mt = 0; mt < 4; mt++) {
            int row = r0 + warpM * 64 + mt * 16 + (lane >> 2);
            *(__half2*)&g_P16[(size_t)row * G4 + ncol] =
                __floats2half2_rn(acc[mt][nt][0] + bv.x, acc[mt][nt][1] + bv.y);
            *(__half2*)&g_P16[(size_t)(row + 8) * G4 + ncol] =
                __floats2half2_rn(acc[mt][nt][2] + bv.x, acc[mt][nt][3] + bv.y);
        }
    }
}

// ---------------- grid barrier ----------------
__device__ __forceinline__ void grid_bar(int target) {
    __threadfence();
    __syncthreads();
    if (threadIdx.x == 0) {
        int v = atomicAdd(&g_bar_count, 1);
        if (v == NBLK - 1) {
            g_bar_count = 0;
            __threadfence();
            g_phase = target;
        } else {
            while (g_phase < target) __nanosleep(32);
        }
    }
    __syncthreads();
}

// ---------------- persistent recurrent layer: K=128 chunks, B-loads hoisted across barrier ----------------
__global__ void __launch_bounds__(256, 1) recur16(int layer) {
    extern __shared__ char smem[];
    __half* sA = (__half*)smem;                   // 2 x 16384 halves
    uint32_t* sB = (uint32_t*)(smem + RB_OFF);    // 2 x 8192 u32
    __half* sP = (__half*)(smem + RSP_OFF);
    const uint32_t saddr = (uint32_t)__cvta_generic_to_shared(smem);

    const int tid = threadIdx.x, lane = tid & 31, wid = tid >> 5;
    const int warpM = wid >> 2, warpN = wid & 3;
    const int n8base = blockIdx.x * 16;
    const int n0 = blockIdx.x * 128;
    const int r0 = blockIdx.y * 128;

    __half* Hbuf = g_H16[layer & 1];
    const uint32_t* __restrict__ W = g_WrH + (size_t)layer * (HHD * G4 / 2);
    const int base = g_phase;

    const int quad = lane >> 3, rr8 = lane & 7;
    const int gsel = quad >> 1;
    const uint32_t abase = saddr + (uint32_t)(warpM * 64 + rr8 + (quad & 1) * 8) * 256;

    float cst[4][2][2];
#pragma unroll
    for (int mt = 0; mt < 4; mt++)
#pragma unroll
        for (int rr = 0; rr < 2; rr++) { cst[mt][rr][0] = 0.f; cst[mt][rr][1] = 0.f; }

    const int j0 = blockIdx.x * 32 + warpN * 8 + (lane & 3) * 2;

    // loaders (no commit inside; caller commits to control grouping)
    auto loadA = [&](const __half* A, int kc, int s) {
        __half* sa = sA + s * 16384;
#pragma unroll
        for (int i = 0; i < 8; i++) {
            int u = i * 256 + tid;
            int row = u >> 4, seg = u & 15;
            cp16(sa + row * 128 + ((seg ^ (row & 7)) * 8),
                 A + (size_t)(r0 + row) * HHD + kc * 128 + seg * 8);
        }
    };
    auto loadB = [&](int kc, int s) {
        uint32_t* sb = sB + s * 8192;
#pragma unroll
        for (int k16l = 0; k16l < 8; k16l++) {
            cp16(sb + k16l * 1024 + tid * 4,
                 W + ((size_t)(kc * 8 + k16l) * 256 + n8base) * 64 + tid * 4);
        }
    };
    auto loadP = [&](int t) {
        const __half* Pg = g_P16 + (size_t)t * BQ * G4;
#pragma unroll
        for (int i = 0; i < 8; i++) {
            int u = i * 256 + tid;
            int row = u >> 4, seg = u & 15;
            cp16(sP + row * SP_STRIDE + seg * 8,
                 Pg + (size_t)(r0 + row) * G4 + n0 + seg * 8);
        }
    };

    // ---- t = 0: no GEMM; prime B chunks for t=1 ----
    {
        loadP(0); CPCOMMIT();       // group: P0
        loadB(0, 0); CPCOMMIT();    // group: B0 (for t=1)
        loadB(1, 1); CPCOMMIT();    // group: B1
        CPWAIT(2);                  // P0 done; B0,B1 may be in flight
        __syncthreads();

        __half* hout = Hbuf;  // t = 0
#pragma unroll
        for (int mt = 0; mt < 4; mt++) {
#pragma unroll
            for (int rr = 0; rr < 2; rr++) {
                int lrow = warpM * 64 + mt * 16 + (lane >> 2) + rr * 8;
                const __half* prow = sP + (size_t)lrow * SP_STRIDE + warpN * 32 + (lane & 3) * 2;
                float2 pi = __half22float2(*(const __half2*)(prow));
                float2 pf = __half22float2(*(const __half2*)(prow + 8));
                float2 pg = __half22float2(*(const __half2*)(prow + 16));
                float2 po = __half22float2(*(const __half2*)(prow + 24));
                float i0 = sigm(pi.x), i1 = sigm(pi.y);
                float gg0 = tnh(pg.x), gg1 = tnh(pg.y);
                float o0 = sigm(po.x), o1 = sigm(po.y);
                (void)pf;
                float c0 = i0 * gg0;
                float c1 = i1 * gg1;
                cst[mt][rr][0] = c0;
                cst[mt][rr][1] = c1;
                int b = r0 + lrow;
                *(__half2*)&hout[(size_t)b * HHD + j0] =
                    __floats2half2_rn(o0 * tnh(c0), o1 * tnh(c1));
            }
        }
        grid_bar(base + 1);
    }

    // ---- t = 1..63 ----
    for (int t = 1; t < TT; t++) {
        const __half* __restrict__ A = Hbuf + (size_t)(t - 1) * BQ * HHD;
        // after barrier: only P + A chunks on critical path (B0,B1 already in flight)
        loadP(t); loadA(A, 0, 0); CPCOMMIT();  // group A0 (+P)
        loadA(A, 1, 1); CPCOMMIT();           // group A1

        float acc[4][4][4];
#pragma unroll
        for (int mt = 0; mt < 4; mt++)
#pragma unroll
            for (int nt = 0; nt < 4; nt++)
#pragma unroll
                for (int q = 0; q < 4; q++) acc[mt][nt][q] = 0.f;

        for (int kc = 0; kc < 4; kc++) {
            int s = kc & 1;
            if (kc < 3) CPWAIT(1);
            else        CPWAIT(0);
            __syncthreads();
            const uint32_t sa_u = abase + s * 32768;
            const uint32_t* sb = sB + s * 8192;
#pragma unroll
            for (int k16l = 0; k16l < 8; k16l++) {
                const uint32_t grp = (uint32_t)(((k16l * 2 + gsel) ^ rr8) * 16);
                uint32_t a[4][4];
#pragma unroll
                for (int mt = 0; mt < 4; mt++) ldmat4(a[mt], sa_u + mt * 4096 + grp);
#pragma unroll
                for (int nt = 0; nt < 4; nt++) {
                    uint2 b = *(const uint2*)(sb + (k16l * 16 + warpN * 4 + nt) * 64 + lane * 2);
#pragma unroll
                    for (int mt = 0; mt < 4; mt++) mma16(acc[mt][nt], a[mt], b.x, b.y);
                }
            }
            __syncthreads();
            if (kc + 2 < 4) { loadA(A, kc + 2, s); loadB(kc + 2, s); CPCOMMIT(); }
        }

        // buffers free: prime next step's B chunks before epilogue + barrier
        if (t + 1 < TT) {
            loadB(0, 0); CPCOMMIT();
            loadB(1, 1); CPCOMMIT();
        }

        // fused LSTM cell epilogue (P from smem)
        __half* hout = Hbuf + (size_t)t * BQ * HHD;
#pragma unroll
        for (int mt = 0; mt < 4; mt++) {
#pragma unroll
            for (int rr = 0; rr < 2; rr++) {
                int lrow = warpM * 64 + mt * 16 + (lane >> 2) + rr * 8;
                const __half* prow = sP + (size_t)lrow * SP_STRIDE + warpN * 32 + (lane & 3) * 2;
                float2 pi = __half22float2(*(const __half2*)(prow));
                float2 pf = __half22float2(*(const __half2*)(prow + 8));
                float2 pg = __half22float2(*(const __half2*)(prow + 16));
                float2 po = __half22float2(*(const __half2*)(prow + 24));
                float i0 = sigm(acc[mt][0][rr * 2 + 0] + pi.x);
                float i1 = sigm(acc[mt][0][rr * 2 + 1] + pi.y);
                float f0 = sigm(acc[mt][1][rr * 2 + 0] + pf.x);
                float f1 = sigm(acc[mt][1][rr * 2 + 1] + pf.y);
                float gg0 = tnh(acc[mt][2][rr * 2 + 0] + pg.x);
                float gg1 = tnh(acc[mt][2][rr * 2 + 1] + pg.y);
                float o0 = sigm(acc[mt][3][rr * 2 + 0] + po.x);
                float o1 = sigm(acc[mt][3][rr * 2 + 1] + po.y);
                float c0 = f0 * cst[mt][rr][0] + i0 * gg0;
                float c1 = f1 * cst[mt][rr][1] + i1 * gg1;
                cst[mt][rr][0] = c0;
                cst[mt][rr][1] = c1;
                int b = r0 + lrow;
                *(__half2*)&hout[(size_t)b * HHD + j0] =
                    __floats2half2_rn(o0 * tnh(c0), o1 * tnh(c1));
            }
        }
        grid_bar(base + t + 1);
    }
}

// ---------------- final FC: fp16 tensor GEMM split-K over t -> fp32 partials ----------------
__global__ void __launch_bounds__(256, 2) fc16() {
    extern __shared__ char smem[];
    __half* sA = (__half*)smem;
    uint32_t* sB = (uint32_t*)(smem + SB_OFF);
    const uint32_t saddr = (uint32_t)__cvta_generic_to_shared(smem);

    const int tid = threadIdx.x, lane = tid & 31, wid = tid >> 5;
    const int warpM = wid >> 2, warpN = wid & 3;
    const int r0 = blockIdx.x * 128;
    const int t = blockIdx.y;
    const __half* __restrict__ A = g_H16[(LL - 1) & 1] + (size_t)t * BQ * HHD;
    const uint32_t* __restrict__ W = g_FcH + (size_t)t * 32768;

    const int quad = lane >> 3, rr8 = lane & 7;
    const int gsel = quad >> 1;
    const uint32_t abase = saddr + (uint32_t)(warpM * 64 + rr8 + (quad & 1) * 8) * 128;

    float acc[4][4][4];
#pragma unroll
    for (int mt = 0; mt < 4; mt++)
#pragma unroll
        for (int nt = 0; nt < 4; nt++)
#pragma unroll
            for (int q = 0; q < 4; q++) acc[mt][nt][q] = 0.f;

    auto load = [&](int kc, int s) {
        __half* sa = sA + s * 8192;
#pragma unroll
        for (int i = 0; i < 4; i++) {
            int u = i * 256 + tid;
            int row = u >> 3, seg = u & 7;
            cp16(sa + row * 64 + (seg ^ (row & 7)) * 8,
                 A + (size_t)(r0 + row) * HHD + kc * 64 + seg * 8);
        }
        uint32_t* sb = sB + s * 4096;
#pragma unroll
        for (int k16l = 0; k16l < 4; k16l++) {
            cp16(sb + k16l * 1024 + tid * 4,
                 W + (size_t)(kc * 4 + k16l) * 1024 + tid * 4);
        }
        CPCOMMIT();
    };

    load(0, 0);
    load(1, 1);
    for (int kc = 0; kc < 8; kc++) {
        int s = kc & 1;
        if (kc < 6) CPWAIT(1);
        else        CPWAIT(0);
        __syncthreads();
        const uint32_t sa_u = abase + s * 16384;
        const uint32_t* sb = sB + s * 4096;
#pragma unroll
        for (int k16l = 0; k16l < 4; k16l++) {
            const uint32_t grp = (uint32_t)(((k16l * 2 + gsel) ^ rr8) * 16);
            uint32_t a[4][4];
#pragma unroll
            for (int mt = 0; mt < 4; mt++) ldmat4(a[mt], sa_u + mt * 2048 + grp);
#pragma unroll
            for (int nt = 0; nt < 4; nt++) {
                uint2 b = *(const uint2*)(sb + (k16l * 16 + warpN * 4 + nt) * 64 + lane * 2);
#pragma unroll
                for (int mt = 0; mt < 4; mt++) mma16(acc[mt][nt], a[mt], b.x, b.y);
            }
        }
        __syncthreads();
        if (kc + 2 < 8) load(kc + 2, s);
    }

    float* pout = g_fcp + (size_t)t * BQ * CC;
#pragma unroll
    for (int nt = 0; nt < 4; nt++) {
        int ncol = warpN * 32 + nt * 8 + (lane & 3) * 2;
#pragma unroll
        for (int mt = 0; mt < 4; mt++) {
            int row = r0 + warpM * 64 + mt * 16 + (lane >> 2);
            *(float2*)&pout[(size_t)row * CC + ncol] = make_float2(acc[mt][nt][0], acc[mt][nt][1]);
            *(float2*)&pout[(size_t)(row + 8) * CC + ncol] = make_float2(acc[mt][nt][2], acc[mt][nt][3]);
        }
    }
}

__global__ void fc_reduce(const float* __restrict__ fc_b, float* __restrict__ out) {
    int i = blockIdx.x * blockDim.x + threadIdx.x;
    if (i >= BQ * CC) return;
    float s = fc_b[i & (CC - 1)];
#pragma unroll 8
    for (int t = 0; t < TT; t++) s += g_fcp[(size_t)t * BQ * CC + i];
    out[i] = s;
}

// ---------------- launch ----------------
extern "C" void kernel_launch(void* const* d_in, const int* in_sizes, int n_in,
                              void* d_out, int out_size) {
    const float* x     = (const float*)d_in[0];
    const float* w_ih0 = (const float*)d_in[1];
    const float* w_hh0 = (const float*)d_in[2];
    const float* b_ih0 = (const float*)d_in[3];
    const float* b_hh0 = (const float*)d_in[4];
    const float* w_ih  = (const float*)d_in[5];
    const float* w_hh  = (const float*)d_in[6];
    const float* b_ih  = (const float*)d_in[7];
    const float* b_hh  = (const float*)d_in[8];
    const float* fc_w  = (const float*)d_in[9];
    const float* fc_b  = (const float*)d_in[10];
    float* out = (float*)d_out;

    cudaFuncSetAttribute(proj16, cudaFuncAttributeMaxDynamicSharedMemorySize, PROJ_SMEM);
    cudaFuncSetAttribute(recur16, cudaFuncAttributeMaxDynamicSharedMemorySize, RECUR_SMEM);
    cudaFuncSetAttribute(fc16, cudaFuncAttributeMaxDynamicSharedMemorySize, PROJ_SMEM);

    prep_x<<<2048, 256>>>(x);
    prep_wi<<<4096, 256>>>(w_ih0, w_ih);
    prep_wr<<<4096, 256>>>(w_hh0, w_hh);
    prep_fcw<<<2048, 256>>>(fc_w);
    prep_bias<<<64, 256>>>(b_ih0, b_hh0, b_ih, b_hh);

    for (int l = 0; l < LL; l++) {
        proj16<<<dim3(16, 512), 256, PROJ_SMEM>>>(l);
        recur16<<<dim3(16, 8), 256, RECUR_SMEM>>>(l);
    }

    fc16<<<dim3(8, TT), 256, PROJ_SMEM>>>();
    fc_reduce<<<(BQ * CC + 255) / 256, 256>>>(fc_b, out);
}

// round 15
// speedup vs baseline: 1.0416x; 1.0416x over previous
#include <cuda_runtime.h>
#include <cuda_fp16.h>
#include <math.h>
#include <stdint.h>

#define BQ 1024
#define TT 64
#define INDIM 64
#define LL 8
#define HHD 512
#define G4 2048
#define CC 128
#define NBLK 128

// ---------------- device scratch ----------------
__device__ __align__(128) __half g_P16[(size_t)TT * BQ * G4];      // gate preactivations fp16, permuted cols
__device__ __align__(128) __half g_H16[2][(size_t)TT * BQ * HHD];  // hidden seq fp16, ping-pong
__device__ __align__(128) __half g_X16[(size_t)TT * BQ * INDIM];   // x as fp16
__device__ __align__(128) uint32_t g_WiH[((size_t)INDIM + (LL - 1) * HHD) * G4 / 2]; // Wi fragments
__device__ __align__(128) uint32_t g_WrH[(size_t)LL * HHD * G4 / 2];                 // Wr fragments
__device__ __align__(128) uint32_t g_FcH[(size_t)TT * HHD * CC / 2];                 // fc_w fragments per t
__device__ float g_bias[LL * G4];
__device__ float g_fcp[(size_t)TT * BQ * CC];  // FC split-K partials
__device__ int g_bar_count;
__device__ volatile int g_phase;

// hardware tanh (sm_75+): 1 MUFU op
__device__ __forceinline__ float tanha(float x) {
    float y;
    asm("tanh.approx.f32 %0, %1;" : "=f"(y) : "f"(x));
    return y;
}
__device__ __forceinline__ float sigm(float x) { return fmaf(0.5f, tanha(0.5f * x), 0.5f); }
__device__ __forceinline__ float tnh(float x) { return tanha(x); }

__device__ __forceinline__ void cp16(void* dst, const void* src) {
    uint32_t d = (uint32_t)__cvta_generic_to_shared(dst);
    asm volatile("cp.async.cg.shared.global [%0], [%1], 16;" ::"r"(d), "l"(src));
}

__device__ __forceinline__ void mma16(float* c, const uint32_t* a, uint32_t b0, uint32_t b1) {
    asm volatile(
        "mma.sync.aligned.m16n8k16.row.col.f32.f16.f16.f32 "
        "{%0,%1,%2,%3}, {%4,%5,%6,%7}, {%8,%9}, {%0,%1,%2,%3};"
        : "+f"(c[0]), "+f"(c[1]), "+f"(c[2]), "+f"(c[3])
        : "r"(a[0]), "r"(a[1]), "r"(a[2]), "r"(a[3]), "r"(b0), "r"(b1));
}

__device__ __forceinline__ void ldmat4(uint32_t* a, uint32_t addr) {
    asm volatile(
        "ldmatrix.sync.aligned.m8n8.x4.shared.b16 {%0,%1,%2,%3}, [%4];"
        : "=r"(a[0]), "=r"(a[1]), "=r"(a[2]), "=r"(a[3]) : "r"(addr));
}

#define CPCOMMIT() asm volatile("cp.async.commit_group;" ::: "memory")
#define CPWAIT(n) asm volatile("cp.async.wait_group %0;" ::"n"(n) : "memory")

// column permutation: n_log(g, j) = (j>>5)*128 + ((j>>3)&3)*32 + g*8 + (j&7)

// ---------------- weight prep: fp16 fragment images ----------------
__global__ void prep_wi(const float* __restrict__ w_ih0, const float* __restrict__ w_ih) {
    const size_t R0 = (size_t)INDIM * G4 / 2;
    size_t total = R0 + (size_t)(LL - 1) * HHD * G4 / 2;
    size_t stride = (size_t)gridDim.x * blockDim.x;
    for (size_t idx = (size_t)blockIdx.x * blockDim.x + threadIdx.x; idx < total; idx += stride) {
        int l;
        uint32_t rem;
        if (idx < R0) { l = 0; rem = (uint32_t)idx; }
        else { size_t r = idx - R0; l = 1 + (int)(r >> 19); rem = (uint32_t)(r & 524287u); }
        int rr = rem & 1, lane = (rem >> 1) & 31, n8 = (rem >> 6) & 255, k16 = rem >> 14;
        int k0 = k16 * 16 + (lane & 3) * 2 + rr * 8;
        int nlog = n8 * 8 + (lane >> 2);
        int j = ((nlog >> 7) << 5) + (((nlog >> 5) & 3) << 3) + (nlog & 7);
        int g = (nlog >> 3) & 3;
        float v0, v1;
        if (l == 0) {
            const float* p = w_ih0 + (size_t)(g * HHD + j) * INDIM + k0;
            v0 = p[0]; v1 = p[1];
        } else {
            const float* p = w_ih + ((size_t)(l - 1) * G4 + g * HHD + j) * HHD + k0;
            v0 = p[0]; v1 = p[1];
        }
        __half2 h = __floats2half2_rn(v0, v1);
        g_WiH[idx] = *(uint32_t*)&h;
    }
}

__global__ void prep_wr(const float* __restrict__ w_hh0, const float* __restrict__ w_hh) {
    size_t total = (size_t)LL * HHD * G4 / 2;
    size_t stride = (size_t)gridDim.x * blockDim.x;
    for (size_t idx = (size_t)blockIdx.x * blockDim.x + threadIdx.x; idx < total; idx += stride) {
        int l = (int)(idx >> 19);
        uint32_t rem = (uint32_t)(idx & 524287u);
        int rr = rem & 1, lane = (rem >> 1) & 31, n8 = (rem >> 6) & 255, k16 = rem >> 14;
        int k0 = k16 * 16 + (lane & 3) * 2 + rr * 8;
        int nlog = n8 * 8 + (lane >> 2);
        int j = ((nlog >> 7) << 5) + (((nlog >> 5) & 3) << 3) + (nlog & 7);
        int g = (nlog >> 3) & 3;
        float v0, v1;
        if (l == 0) {
            const float* p = w_hh0 + (size_t)(g * HHD + j) * HHD + k0;
            v0 = p[0]; v1 = p[1];
        } else {
            const float* p = w_hh + ((size_t)(l - 1) * G4 + g * HHD + j) * HHD + k0;
            v0 = p[0]; v1 = p[1];
        }
        __half2 h = __floats2half2_rn(v0, v1);
        g_WrH[idx] = *(uint32_t*)&h;
    }
}

// fc_w fragments: per t, [k16(32)][c8(16)][lane(32)][2]; value fc_w[c][t*HHD + k]
__global__ void prep_fcw(const float* __restrict__ fw) {
    size_t total = (size_t)TT * HHD * CC / 2;
    size_t stride = (size_t)gridDim.x * blockDim.x;
    for (size_t idx = (size_t)blockIdx.x * blockDim.x + threadIdx.x; idx < total; idx += stride) {
        uint32_t rem = (uint32_t)(idx & 32767u);
        int t = (int)(idx >> 15);
        int rr = rem & 1, lane = (rem >> 1) & 31, c8 = (rem >> 6) & 15, k16 = rem >> 10;
        int k0 = k16 * 16 + (lane & 3) * 2 + rr * 8;
        int c = c8 * 8 + (lane >> 2);
        const float* p = fw + (size_t)c * (TT * HHD) + (size_t)t * HHD + k0;
        __half2 h = __floats2half2_rn(p[0], p[1]);
        g_FcH[idx] = *(uint32_t*)&h;
    }
}

__global__ void prep_bias(const float* __restrict__ b_ih0, const float* __restrict__ b_hh0,
                          const float* __restrict__ b_ih, const float* __restrict__ b_hh) {
    int idx = blockIdx.x * blockDim.x + threadIdx.x;
    if (idx >= LL * G4) return;
    int l = idx >> 11, nlog = idx & 2047;
    int j = ((nlog >> 7) << 5) + (((nlog >> 5) & 3) << 3) + (nlog & 7);
    int g = (nlog >> 3) & 3;
    float v = (l == 0) ? (b_ih0[g * HHD + j] + b_hh0[g * HHD + j])
                       : (b_ih[(l - 1) * G4 + g * HHD + j] + b_hh[(l - 1) * G4 + g * HHD + j]);
    g_bias[idx] = v;
}

__global__ void prep_x(const float* __restrict__ x) {
    size_t total = (size_t)TT * BQ * INDIM;
    size_t stride = (size_t)gridDim.x * blockDim.x;
    for (size_t idx = (size_t)blockIdx.x * blockDim.x + threadIdx.x; idx < total; idx += stride) {
        int k = (int)(idx & 63);
        int r = (int)(idx >> 6);
        int b = r & (BQ - 1), t = r >> 10;
        g_X16[idx] = __float2half(x[((size_t)b * TT + t) * INDIM + k]);
    }
}

// proj/fc smem: sA[2][128*64 halves]=32768, sB[2][4096 u32]=32768
#define SB_OFF 32768
#define PROJ_SMEM 65536
// recur smem (K=128 chunks): sA[2][128*128 halves]=65536, sB[2][8192 u32]=65536 @65536,
// sP 128 x 136-half stride = 34816 @131072
#define RB_OFF 65536
#define RSP_OFF 131072
#define SP_STRIDE 136
#define RECUR_SMEM (RSP_OFF + 128 * SP_STRIDE * 2)

// ---------------- input projection: fp16 tensor GEMM (R13 winner, unchanged) ----------------
__global__ void __launch_bounds__(256, 2) proj16(int layer) {
    extern __shared__ char smem[];
    __half* sA = (__half*)smem;
    uint32_t* sB = (uint32_t*)(smem + SB_OFF);
    const uint32_t saddr = (uint32_t)__cvta_generic_to_shared(smem);

    const int tid = threadIdx.x, lane = tid & 31, wid = tid >> 5;
    const int warpM = wid >> 2, warpN = wid & 3;
    const int n8base = blockIdx.x * 16;
    const int n0 = blockIdx.x * 128;
    const int r0 = blockIdx.y * 128;
    const int K = (layer == 0) ? INDIM : HHD;
    const int NC = K / 64;
    const __half* __restrict__ A = (layer == 0) ? g_X16 : g_H16[(layer - 1) & 1];
    const uint32_t* __restrict__ W =
        g_WiH + ((layer == 0) ? (size_t)0 : (size_t)(INDIM * G4 / 2) + (size_t)(layer - 1) * (HHD * G4 / 2));

    const int quad = lane >> 3, rr8 = lane & 7;
    const int gsel = quad >> 1;
    const uint32_t abase = saddr + (uint32_t)(warpM * 64 + rr8 + (quad & 1) * 8) * 128;

    float acc[4][4][4];
#pragma unroll
    for (int mt = 0; mt < 4; mt++)
#pragma unroll
        for (int nt = 0; nt < 4; nt++)
#pragma unroll
            for (int q = 0; q < 4; q++) acc[mt][nt][q] = 0.f;

    auto load = [&](int kc, int s) {
        __half* sa = sA + s * 8192;
#pragma unroll
        for (int i = 0; i < 4; i++) {
            int u = i * 256 + tid;
            int row = u >> 3, seg = u & 7;
            cp16(sa + row * 64 + (seg ^ (row & 7)) * 8,
                 A + (size_t)(r0 + row) * K + kc * 64 + seg * 8);
        }
        uint32_t* sb = sB + s * 4096;
#pragma unroll
        for (int k16l = 0; k16l < 4; k16l++) {
            cp16(sb + k16l * 1024 + tid * 4,
                 W + ((size_t)(kc * 4 + k16l) * 256 + n8base) * 64 + tid * 4);
        }
        CPCOMMIT();
    };

    load(0, 0);
    if (NC > 1) load(1, 1);
    for (int kc = 0; kc < NC; kc++) {
        int s = kc & 1;
        if (kc + 2 <= NC) CPWAIT(1);
        else              CPWAIT(0);
        __syncthreads();
        const uint32_t sa_u = abase + s * 16384;
        const uint32_t* sb = sB + s * 4096;
#pragma unroll
        for (int k16l = 0; k16l < 4; k16l++) {
            const uint32_t grp = (uint32_t)(((k16l * 2 + gsel) ^ rr8) * 16);
            uint32_t a[4][4];
#pragma unroll
            for (int mt = 0; mt < 4; mt++) ldmat4(a[mt], sa_u + mt * 2048 + grp);
#pragma unroll
            for (int nt = 0; nt < 4; nt++) {
                uint2 b = *(const uint2*)(sb + (k16l * 16 + warpN * 4 + nt) * 64 + lane * 2);
#pragma unroll
                for (int mt = 0; mt < 4; mt++) mma16(acc[mt][nt], a[mt], b.x, b.y);
            }
        }
        __syncthreads();
        if (kc + 2 < NC) load(kc + 2, s);
    }

    const float* __restrict__ bias = g_bias + layer * G4;
#pragma unroll
    for (int nt = 0; nt < 4; nt++) {
        int ncol = n0 + warpN * 32 + nt * 8 + (lane & 3) * 2;
        float2 bv = *(const float2*)&bias[ncol];
#pragma unroll
        for (int mt = 0; mt < 4; mt++) {
            int row = r0 + warpM * 64 + mt * 16 + (lane >> 2);
            *(__half2*)&g_P16[(size_t)row * G4 + ncol] =
                __floats2half2_rn(acc[mt][nt][0] + bv.x, acc[mt][nt][1] + bv.y);
            *(__half2*)&g_P16[(size_t)(row + 8) * G4 + ncol] =
                __floats2half2_rn(acc[mt][nt][2] + bv.x, acc[mt][nt][3] + bv.y);
        }
    }
}

// ---------------- grid barrier ----------------
__device__ __forceinline__ void grid_bar(int target) {
    __threadfence();
    __syncthreads();
    if (threadIdx.x == 0) {
        int v = atomicAdd(&g_bar_count, 1);
        if (v == NBLK - 1) {
            g_bar_count = 0;
            __threadfence();
            g_phase = target;
        } else {
            while (g_phase < target) __nanosleep(32);
        }
    }
    __syncthreads();
}

// ---------------- persistent recurrent layer: K=128 chunks (R13 winner structure) ----------------
__global__ void __launch_bounds__(256, 1) recur16(int layer) {
    extern __shared__ char smem[];
    __half* sA = (__half*)smem;                   // 2 x 16384 halves (row stride 128)
    uint32_t* sB = (uint32_t*)(smem + RB_OFF);    // 2 x 8192 u32
    __half* sP = (__half*)(smem + RSP_OFF);
    const uint32_t saddr = (uint32_t)__cvta_generic_to_shared(smem);

    const int tid = threadIdx.x, lane = tid & 31, wid = tid >> 5;
    const int warpM = wid >> 2, warpN = wid & 3;
    const int n8base = blockIdx.x * 16;
    const int n0 = blockIdx.x * 128;
    const int r0 = blockIdx.y * 128;

    __half* Hbuf = g_H16[layer & 1];
    const uint32_t* __restrict__ W = g_WrH + (size_t)layer * (HHD * G4 / 2);
    const int base = g_phase;

    const int quad = lane >> 3, rr8 = lane & 7;
    const int gsel = quad >> 1;
    const uint32_t abase = saddr + (uint32_t)(warpM * 64 + rr8 + (quad & 1) * 8) * 256;

    float cst[4][2][2];
#pragma unroll
    for (int mt = 0; mt < 4; mt++)
#pragma unroll
        for (int rr = 0; rr < 2; rr++) { cst[mt][rr][0] = 0.f; cst[mt][rr][1] = 0.f; }

    const int j0 = blockIdx.x * 32 + warpN * 8 + (lane & 3) * 2;

    for (int t = 0; t < TT; t++) {
        // prefetch P tile into smem (joins first commit group of this step)
        {
            const __half* Pg = g_P16 + (size_t)t * BQ * G4;
#pragma unroll
            for (int i = 0; i < 8; i++) {
                int u = i * 256 + tid;
                int row = u >> 4, seg = u & 15;
                cp16(sP + row * SP_STRIDE + seg * 8,
                     Pg + (size_t)(r0 + row) * G4 + n0 + seg * 8);
            }
        }

        float acc[4][4][4];
#pragma unroll
        for (int mt = 0; mt < 4; mt++)
#pragma unroll
            for (int nt = 0; nt < 4; nt++)
#pragma unroll
                for (int q = 0; q < 4; q++) acc[mt][nt][q] = 0.f;

        if (t > 0) {
            const __half* __restrict__ A = Hbuf + (size_t)(t - 1) * BQ * HHD;
            auto load = [&](int kc, int s) {
                __half* sa = sA + s * 16384;
#pragma unroll
                for (int i = 0; i < 8; i++) {
                    int u = i * 256 + tid;
                    int row = u >> 4, seg = u & 15;
                    cp16(sa + row * 128 + ((seg ^ (row & 7)) * 8),
                         A + (size_t)(r0 + row) * HHD + kc * 128 + seg * 8);
                }
                uint32_t* sb = sB + s * 8192;
#pragma unroll
                for (int k16l = 0; k16l < 8; k16l++) {
                    cp16(sb + k16l * 1024 + tid * 4,
                         W + ((size_t)(kc * 8 + k16l) * 256 + n8base) * 64 + tid * 4);
                }
                CPCOMMIT();
            };

            load(0, 0);
            load(1, 1);
            for (int kc = 0; kc < 4; kc++) {
                int s = kc & 1;
                if (kc < 3) CPWAIT(1);
                else        CPWAIT(0);
                __syncthreads();
                const uint32_t sa_u = abase + s * 32768;
                const uint32_t* sb = sB + s * 8192;
#pragma unroll
                for (int k16l = 0; k16l < 8; k16l++) {
                    const uint32_t grp = (uint32_t)(((k16l * 2 + gsel) ^ rr8) * 16);
                    uint32_t a[4][4];
#pragma unroll
                    for (int mt = 0; mt < 4; mt++) ldmat4(a[mt], sa_u + mt * 4096 + grp);
#pragma unroll
                    for (int nt = 0; nt < 4; nt++) {
                        uint2 b = *(const uint2*)(sb + (k16l * 16 + warpN * 4 + nt) * 64 + lane * 2);
#pragma unroll
                        for (int mt = 0; mt < 4; mt++) mma16(acc[mt][nt], a[mt], b.x, b.y);
                    }
                }
                __syncthreads();
                if (kc + 2 < 4) load(kc + 2, s);
            }
        } else {
            CPCOMMIT();
            CPWAIT(0);
            __syncthreads();
        }

        // fused LSTM cell epilogue (P from smem; hw tanh)
        __half* hout = Hbuf + (size_t)t * BQ * HHD;
#pragma unroll
        for (int mt = 0; mt < 4; mt++) {
#pragma unroll
            for (int rr = 0; rr < 2; rr++) {
                int lrow = warpM * 64 + mt * 16 + (lane >> 2) + rr * 8;
                const __half* prow = sP + (size_t)lrow * SP_STRIDE + warpN * 32 + (lane & 3) * 2;
                float2 pi = __half22float2(*(const __half2*)(prow));
                float2 pf = __half22float2(*(const __half2*)(prow + 8));
                float2 pg = __half22float2(*(const __half2*)(prow + 16));
                float2 po = __half22float2(*(const __half2*)(prow + 24));
                float i0 = sigm(acc[mt][0][rr * 2 + 0] + pi.x);
                float i1 = sigm(acc[mt][0][rr * 2 + 1] + pi.y);
                float f0 = sigm(acc[mt][1][rr * 2 + 0] + pf.x);
                float f1 = sigm(acc[mt][1][rr * 2 + 1] + pf.y);
                float gg0 = tnh(acc[mt][2][rr * 2 + 0] + pg.x);
                float gg1 = tnh(acc[mt][2][rr * 2 + 1] + pg.y);
                float o0 = sigm(acc[mt][3][rr * 2 + 0] + po.x);
                float o1 = sigm(acc[mt][3][rr * 2 + 1] + po.y);
                float c0 = f0 * cst[mt][rr][0] + i0 * gg0;
                float c1 = f1 * cst[mt][rr][1] + i1 * gg1;
                cst[mt][rr][0] = c0;
                cst[mt][rr][1] = c1;
                int b = r0 + lrow;
                *(__half2*)&hout[(size_t)b * HHD + j0] =
                    __floats2half2_rn(o0 * tnh(c0), o1 * tnh(c1));
            }
        }
        grid_bar(base + t + 1);
    }
}

// ---------------- final FC: fp16 tensor GEMM split-K over t -> fp32 partials ----------------
__global__ void __launch_bounds__(256, 2) fc16() {
    extern __shared__ char smem[];
    __half* sA = (__half*)smem;
    uint32_t* sB = (uint32_t*)(smem + SB_OFF);
    const uint32_t saddr = (uint32_t)__cvta_generic_to_shared(smem);

    const int tid = threadIdx.x, lane = tid & 31, wid = tid >> 5;
    const int warpM = wid >> 2, warpN = wid & 3;
    const int r0 = blockIdx.x * 128;
    const int t = blockIdx.y;
    const __half* __restrict__ A = g_H16[(LL - 1) & 1] + (size_t)t * BQ * HHD;
    const uint32_t* __restrict__ W = g_FcH + (size_t)t * 32768;

    const int quad = lane >> 3, rr8 = lane & 7;
    const int gsel = quad >> 1;
    const uint32_t abase = saddr + (uint32_t)(warpM * 64 + rr8 + (quad & 1) * 8) * 128;

    float acc[4][4][4];
#pragma unroll
    for (int mt = 0; mt < 4; mt++)
#pragma unroll
        for (int nt = 0; nt < 4; nt++)
#pragma unroll
            for (int q = 0; q < 4; q++) acc[mt][nt][q] = 0.f;

    auto load = [&](int kc, int s) {
        __half* sa = sA + s * 8192;
#pragma unroll
        for (int i = 0; i < 4; i++) {
            int u = i * 256 + tid;
            int row = u >> 3, seg = u & 7;
            cp16(sa + row * 64 + (seg ^ (row & 7)) * 8,
                 A + (size_t)(r0 + row) * HHD + kc * 64 + seg * 8);
        }
        uint32_t* sb = sB + s * 4096;
#pragma unroll
        for (int k16l = 0; k16l < 4; k16l++) {
            cp16(sb + k16l * 1024 + tid * 4,
                 W + (size_t)(kc * 4 + k16l) * 1024 + tid * 4);
        }
        CPCOMMIT();
    };

    load(0, 0);
    load(1, 1);
    for (int kc = 0; kc < 8; kc++) {
        int s = kc & 1;
        if (kc < 6) CPWAIT(1);
        else        CPWAIT(0);
        __syncthreads();
        const uint32_t sa_u = abase + s * 16384;
        const uint32_t* sb = sB + s * 4096;
#pragma unroll
        for (int k16l = 0; k16l < 4; k16l++) {
            const uint32_t grp = (uint32_t)(((k16l * 2 + gsel) ^ rr8) * 16);
            uint32_t a[4][4];
#pragma unroll
            for (int mt = 0; mt < 4; mt++) ldmat4(a[mt], sa_u + mt * 2048 + grp);
#pragma unroll
            for (int nt = 0; nt < 4; nt++) {
                uint2 b = *(const uint2*)(sb + (k16l * 16 + warpN * 4 + nt) * 64 + lane * 2);
#pragma unroll
                for (int mt = 0; mt < 4; mt++) mma16(acc[mt][nt], a[mt], b.x, b.y);
            }
        }
        __syncthreads();
        if (kc + 2 < 8) load(kc + 2, s);
    }

    float* pout = g_fcp + (size_t)t * BQ * CC;
#pragma unroll
    for (int nt = 0; nt < 4; nt++) {
        int ncol = warpN * 32 + nt * 8 + (lane & 3) * 2;
#pragma unroll
        for (int mt = 0; mt < 4; mt++) {
            int row = r0 + warpM * 64 + mt * 16 + (lane >> 2);
            *(float2*)&pout[(size_t)row * CC + ncol] = make_float2(acc[mt][nt][0], acc[mt][nt][1]);
            *(float2*)&pout[(size_t)(row + 8) * CC + ncol] = make_float2(acc[mt][nt][2], acc[mt][nt][3]);
        }
    }
}

__global__ void fc_reduce(const float* __restrict__ fc_b, float* __restrict__ out) {
    int i = blockIdx.x * blockDim.x + threadIdx.x;
    if (i >= BQ * CC) return;
    float s = fc_b[i & (CC - 1)];
#pragma unroll 8
    for (int t = 0; t < TT; t++) s += g_fcp[(size_t)t * BQ * CC + i];
    out[i] = s;
}

// ---------------- launch ----------------
extern "C" void kernel_launch(void* const* d_in, const int* in_sizes, int n_in,
                              void* d_out, int out_size) {
    const float* x     = (const float*)d_in[0];
    const float* w_ih0 = (const float*)d_in[1];
    const float* w_hh0 = (const float*)d_in[2];
    const float* b_ih0 = (const float*)d_in[3];
    const float* b_hh0 = (const float*)d_in[4];
    const float* w_ih  = (const float*)d_in[5];
    const float* w_hh  = (const float*)d_in[6];
    const float* b_ih  = (const float*)d_in[7];
    const float* b_hh  = (const float*)d_in[8];
    const float* fc_w  = (const float*)d_in[9];
    const float* fc_b  = (const float*)d_in[10];
    float* out = (float*)d_out;

    cudaFuncSetAttribute(proj16, cudaFuncAttributeMaxDynamicSharedMemorySize, PROJ_SMEM);
    cudaFuncSetAttribute(recur16, cudaFuncAttributeMaxDynamicSharedMemorySize, RECUR_SMEM);
    cudaFuncSetAttribute(fc16, cudaFuncAttributeMaxDynamicSharedMemorySize, PROJ_SMEM);

    prep_x<<<2048, 256>>>(x);
    prep_wi<<<4096, 256>>>(w_ih0, w_ih);
    prep_wr<<<4096, 256>>>(w_hh0, w_hh);
    prep_fcw<<<2048, 256>>>(fc_w);
    prep_bias<<<64, 256>>>(b_ih0, b_hh0, b_ih, b_hh);

    for (int l = 0; l < LL; l++) {
        proj16<<<dim3(16, 512), 256, PROJ_SMEM>>>(l);
        recur16<<<dim3(16, 8), 256, RECUR_SMEM>>>(l);
    }

    fc16<<<dim3(8, TT), 256, PROJ_SMEM>>>();
    fc_reduce<<<(BQ * CC + 255) / 256, 256>>>(fc_b, out);
}

// round 16
// speedup vs baseline: 1.0517x; 1.0097x over previous
#include <cuda_runtime.h>
#include <cuda_fp16.h>
#include <math.h>
#include <stdint.h>

#define BQ 1024
#define TT 64
#define INDIM 64
#define LL 8
#define HHD 512
#define G4 2048
#define CC 128

// ---------------- device scratch ----------------
__device__ __align__(128) __half g_P16[(size_t)TT * BQ * G4];      // gate preactivations fp16, permuted cols
__device__ __align__(128) __half g_H16[2][(size_t)TT * BQ * HHD];  // hidden seq fp16, ping-pong
__device__ __align__(128) __half g_X16[(size_t)TT * BQ * INDIM];   // x as fp16
__device__ __align__(128) uint32_t g_WiH[((size_t)INDIM + (LL - 1) * HHD) * G4 / 2]; // Wi fragments
__device__ __align__(128) uint32_t g_WrH[(size_t)LL * HHD * G4 / 2];                 // Wr fragments
__device__ __align__(128) uint32_t g_FcH[(size_t)TT * HHD * CC / 2];                 // fc_w fragments per t
__device__ float g_bias[LL * G4];
__device__ float g_fcp[(size_t)TT * BQ * CC];  // FC split-K partials
__device__ int g_cnt2[8 * 32];                 // per-row-group barrier counters (128B apart)
__device__ volatile int g_ph2[8 * 32];         // per-row-group phases (monotonic)

// hardware tanh (sm_75+): 1 MUFU op
__device__ __forceinline__ float tanha(float x) {
    float y;
    asm("tanh.approx.f32 %0, %1;" : "=f"(y) : "f"(x));
    return y;
}
__device__ __forceinline__ float sigm(float x) { return fmaf(0.5f, tanha(0.5f * x), 0.5f); }
__device__ __forceinline__ float tnh(float x) { return tanha(x); }

__device__ __forceinline__ void cp16(void* dst, const void* src) {
    uint32_t d = (uint32_t)__cvta_generic_to_shared(dst);
    asm volatile("cp.async.cg.shared.global [%0], [%1], 16;" ::"r"(d), "l"(src));
}

__device__ __forceinline__ void mma16(float* c, const uint32_t* a, uint32_t b0, uint32_t b1) {
    asm volatile(
        "mma.sync.aligned.m16n8k16.row.col.f32.f16.f16.f32 "
        "{%0,%1,%2,%3}, {%4,%5,%6,%7}, {%8,%9}, {%0,%1,%2,%3};"
        : "+f"(c[0]), "+f"(c[1]), "+f"(c[2]), "+f"(c[3])
        : "r"(a[0]), "r"(a[1]), "r"(a[2]), "r"(a[3]), "r"(b0), "r"(b1));
}

__device__ __forceinline__ void ldmat4(uint32_t* a, uint32_t addr) {
    asm volatile(
        "ldmatrix.sync.aligned.m8n8.x4.shared.b16 {%0,%1,%2,%3}, [%4];"
        : "=r"(a[0]), "=r"(a[1]), "=r"(a[2]), "=r"(a[3]) : "r"(addr));
}

#define CPCOMMIT() asm volatile("cp.async.commit_group;" ::: "memory")
#define CPWAIT(n) asm volatile("cp.async.wait_group %0;" ::"n"(n) : "memory")

// column permutation: n_log(g, j) = (j>>5)*128 + ((j>>3)&3)*32 + g*8 + (j&7)

// ---------------- weight prep: fp16 fragment images ----------------
__global__ void prep_wi(const float* __restrict__ w_ih0, const float* __restrict__ w_ih) {
    const size_t R0 = (size_t)INDIM * G4 / 2;
    size_t total = R0 + (size_t)(LL - 1) * HHD * G4 / 2;
    size_t stride = (size_t)gridDim.x * blockDim.x;
    for (size_t idx = (size_t)blockIdx.x * blockDim.x + threadIdx.x; idx < total; idx += stride) {
        int l;
        uint32_t rem;
        if (idx < R0) { l = 0; rem = (uint32_t)idx; }
        else { size_t r = idx - R0; l = 1 + (int)(r >> 19); rem = (uint32_t)(r & 524287u); }
        int rr = rem & 1, lane = (rem >> 1) & 31, n8 = (rem >> 6) & 255, k16 = rem >> 14;
        int k0 = k16 * 16 + (lane & 3) * 2 + rr * 8;
        int nlog = n8 * 8 + (lane >> 2);
        int j = ((nlog >> 7) << 5) + (((nlog >> 5) & 3) << 3) + (nlog & 7);
        int g = (nlog >> 3) & 3;
        float v0, v1;
        if (l == 0) {
            const float* p = w_ih0 + (size_t)(g * HHD + j) * INDIM + k0;
            v0 = p[0]; v1 = p[1];
        } else {
            const float* p = w_ih + ((size_t)(l - 1) * G4 + g * HHD + j) * HHD + k0;
            v0 = p[0]; v1 = p[1];
        }
        __half2 h = __floats2half2_rn(v0, v1);
        g_WiH[idx] = *(uint32_t*)&h;
    }
}

__global__ void prep_wr(const float* __restrict__ w_hh0, const float* __restrict__ w_hh) {
    size_t total = (size_t)LL * HHD * G4 / 2;
    size_t stride = (size_t)gridDim.x * blockDim.x;
    for (size_t idx = (size_t)blockIdx.x * blockDim.x + threadIdx.x; idx < total; idx += stride) {
        int l = (int)(idx >> 19);
        uint32_t rem = (uint32_t)(idx & 524287u);
        int rr = rem & 1, lane = (rem >> 1) & 31, n8 = (rem >> 6) & 255, k16 = rem >> 14;
        int k0 = k16 * 16 + (lane & 3) * 2 + rr * 8;
        int nlog = n8 * 8 + (lane >> 2);
        int j = ((nlog >> 7) << 5) + (((nlog >> 5) & 3) << 3) + (nlog & 7);
        int g = (nlog >> 3) & 3;
        float v0, v1;
        if (l == 0) {
            const float* p = w_hh0 + (size_t)(g * HHD + j) * HHD + k0;
            v0 = p[0]; v1 = p[1];
        } else {
            const float* p = w_hh + ((size_t)(l - 1) * G4 + g * HHD + j) * HHD + k0;
            v0 = p[0]; v1 = p[1];
        }
        __half2 h = __floats2half2_rn(v0, v1);
        g_WrH[idx] = *(uint32_t*)&h;
    }
}

// fc_w fragments: per t, [k16(32)][c8(16)][lane(32)][2]; value fc_w[c][t*HHD + k]
__global__ void prep_fcw(const float* __restrict__ fw) {
    size_t total = (size_t)TT * HHD * CC / 2;
    size_t stride = (size_t)gridDim.x * blockDim.x;
    for (size_t idx = (size_t)blockIdx.x * blockDim.x + threadIdx.x; idx < total; idx += stride) {
        uint32_t rem = (uint32_t)(idx & 32767u);
        int t = (int)(idx >> 15);
        int rr = rem & 1, lane = (rem >> 1) & 31, c8 = (rem >> 6) & 15, k16 = rem >> 10;
        int k0 = k16 * 16 + (lane & 3) * 2 + rr * 8;
        int c = c8 * 8 + (lane >> 2);
        const float* p = fw + (size_t)c * (TT * HHD) + (size_t)t * HHD + k0;
        __half2 h = __floats2half2_rn(p[0], p[1]);
        g_FcH[idx] = *(uint32_t*)&h;
    }
}

__global__ void prep_bias(const float* __restrict__ b_ih0, const float* __restrict__ b_hh0,
                          const float* __restrict__ b_ih, const float* __restrict__ b_hh) {
    int idx = blockIdx.x * blockDim.x + threadIdx.x;
    if (idx >= LL * G4) return;
    int l = idx >> 11, nlog = idx & 2047;
    int j = ((nlog >> 7) << 5) + (((nlog >> 5) & 3) << 3) + (nlog & 7);
    int g = (nlog >> 3) & 3;
    float v = (l == 0) ? (b_ih0[g * HHD + j] + b_hh0[g * HHD + j])
                       : (b_ih[(l - 1) * G4 + g * HHD + j] + b_hh[(l - 1) * G4 + g * HHD + j]);
    g_bias[idx] = v;
}

__global__ void prep_x(const float* __restrict__ x) {
    size_t total = (size_t)TT * BQ * INDIM;
    size_t stride = (size_t)gridDim.x * blockDim.x;
    for (size_t idx = (size_t)blockIdx.x * blockDim.x + threadIdx.x; idx < total; idx += stride) {
        int k = (int)(idx & 63);
        int r = (int)(idx >> 6);
        int b = r & (BQ - 1), t = r >> 10;
        g_X16[idx] = __float2half(x[((size_t)b * TT + t) * INDIM + k]);
    }
}

// proj/fc smem: sA[2][128*64 halves]=32768, sB[2][4096 u32]=32768
#define SB_OFF 32768
#define PROJ_SMEM 65536
// recur smem (K=128 chunks): sA[2][128*128 halves]=65536, sB[2][8192 u32]=65536 @65536,
// sP 128 x 136-half stride = 34816 @131072
#define RB_OFF 65536
#define RSP_OFF 131072
#define SP_STRIDE 136
#define RECUR_SMEM (RSP_OFF + 128 * SP_STRIDE * 2)

// ---------------- input projection: fp16 tensor GEMM (unchanged) ----------------
__global__ void __launch_bounds__(256, 2) proj16(int layer) {
    extern __shared__ char smem[];
    __half* sA = (__half*)smem;
    uint32_t* sB = (uint32_t*)(smem + SB_OFF);
    const uint32_t saddr = (uint32_t)__cvta_generic_to_shared(smem);

    const int tid = threadIdx.x, lane = tid & 31, wid = tid >> 5;
    const int warpM = wid >> 2, warpN = wid & 3;
    const int n8base = blockIdx.x * 16;
    const int n0 = blockIdx.x * 128;
    const int r0 = blockIdx.y * 128;
    const int K = (layer == 0) ? INDIM : HHD;
    const int NC = K / 64;
    const __half* __restrict__ A = (layer == 0) ? g_X16 : g_H16[(layer - 1) & 1];
    const uint32_t* __restrict__ W =
        g_WiH + ((layer == 0) ? (size_t)0 : (size_t)(INDIM * G4 / 2) + (size_t)(layer - 1) * (HHD * G4 / 2));

    const int quad = lane >> 3, rr8 = lane & 7;
    const int gsel = quad >> 1;
    const uint32_t abase = saddr + (uint32_t)(warpM * 64 + rr8 + (quad & 1) * 8) * 128;

    float acc[4][4][4];
#pragma unroll
    for (int mt = 0; mt < 4; mt++)
#pragma unroll
        for (int nt = 0; nt < 4; nt++)
#pragma unroll
            for (int q = 0; q < 4; q++) acc[mt][nt][q] = 0.f;

    auto load = [&](int kc, int s) {
        __half* sa = sA + s * 8192;
#pragma unroll
        for (int i = 0; i < 4; i++) {
            int u = i * 256 + tid;
            int row = u >> 3, seg = u & 7;
            cp16(sa + row * 64 + (seg ^ (row & 7)) * 8,
                 A + (size_t)(r0 + row) * K + kc * 64 + seg * 8);
        }
        uint32_t* sb = sB + s * 4096;
#pragma unroll
        for (int k16l = 0; k16l < 4; k16l++) {
            cp16(sb + k16l * 1024 + tid * 4,
                 W + ((size_t)(kc * 4 + k16l) * 256 + n8base) * 64 + tid * 4);
        }
        CPCOMMIT();
    };

    load(0, 0);
    if (NC > 1) load(1, 1);
    for (int kc = 0; kc < NC; kc++) {
        int s = kc & 1;
        if (kc + 2 <= NC) CPWAIT(1);
        else              CPWAIT(0);
        __syncthreads();
        const uint32_t sa_u = abase + s * 16384;
        const uint32_t* sb = sB + s * 4096;
#pragma unroll
        for (int k16l = 0; k16l < 4; k16l++) {
            const uint32_t grp = (uint32_t)(((k16l * 2 + gsel) ^ rr8) * 16);
            uint32_t a[4][4];
#pragma unroll
            for (int mt = 0; mt < 4; mt++) ldmat4(a[mt], sa_u + mt * 2048 + grp);
#pragma unroll
            for (int nt = 0; nt < 4; nt++) {
                uint2 b = *(const uint2*)(sb + (k16l * 16 + warpN * 4 + nt) * 64 + lane * 2);
#pragma unroll
                for (int mt = 0; mt < 4; mt++) mma16(acc[mt][nt], a[mt], b.x, b.y);
            }
        }
        __syncthreads();
        if (kc + 2 < NC) load(kc + 2, s);
    }

    const float* __restrict__ bias = g_bias + layer * G4;
#pragma unroll
    for (int nt = 0; nt < 4; nt++) {
        int ncol = n0 + warpN * 32 + nt * 8 + (lane & 3) * 2;
        float2 bv = *(const float2*)&bias[ncol];
#pragma unroll
        for (int mt = 0; mt < 4; mt++) {
            int row = r0 + warpM * 64 + mt * 16 + (lane >> 2);
            *(__half2*)&g_P16[(size_t)row * G4 + ncol] =
                __floats2half2_rn(acc[mt][nt][0] + bv.x, acc[mt][nt][1] + bv.y);
            *(__half2*)&g_P16[(size_t)(row + 8) * G4 + ncol] =
                __floats2half2_rn(acc[mt][nt][2] + bv.x, acc[mt][nt][3] + bv.y);
        }
    }
}

// ---------------- per-row-group barrier: 16 blocks sharing by ----------------
__device__ __forceinline__ void group_bar(int slot, int target) {
    __threadfence();
    __syncthreads();
    if (threadIdx.x == 0) {
        int v = atomicAdd(&g_cnt2[slot], 1);
        if (v == 15) {
            g_cnt2[slot] = 0;
            __threadfence();
            g_ph2[slot] = target;
        } else {
            while (g_ph2[slot] < target) __nanosleep(32);
        }
    }
    __syncthreads();
}

// ---------------- persistent recurrent layer: K=128 chunks, split barriers ----------------
__global__ void __launch_bounds__(256, 1) recur16(int layer) {
    extern __shared__ char smem[];
    __half* sA = (__half*)smem;                   // 2 x 16384 halves (row stride 128)
    uint32_t* sB = (uint32_t*)(smem + RB_OFF);    // 2 x 8192 u32
    __half* sP = (__half*)(smem + RSP_OFF);
    const uint32_t saddr = (uint32_t)__cvta_generic_to_shared(smem);

    const int tid = threadIdx.x, lane = tid & 31, wid = tid >> 5;
    const int warpM = wid >> 2, warpN = wid & 3;
    const int n8base = blockIdx.x * 16;
    const int n0 = blockIdx.x * 128;
    const int r0 = blockIdx.y * 128;
    const int slot = blockIdx.y * 32;

    __half* Hbuf = g_H16[layer & 1];
    const uint32_t* __restrict__ W = g_WrH + (size_t)layer * (HHD * G4 / 2);
    const int base = g_ph2[slot];

    const int quad = lane >> 3, rr8 = lane & 7;
    const int gsel = quad >> 1;
    const uint32_t abase = saddr + (uint32_t)(warpM * 64 + rr8 + (quad & 1) * 8) * 256;

    float cst[4][2][2];
#pragma unroll
    for (int mt = 0; mt < 4; mt++)
#pragma unroll
        for (int rr = 0; rr < 2; rr++) { cst[mt][rr][0] = 0.f; cst[mt][rr][1] = 0.f; }

    const int j0 = blockIdx.x * 32 + warpN * 8 + (lane & 3) * 2;

    for (int t = 0; t < TT; t++) {
        // prefetch P tile into smem (joins first commit group of this step)
        {
            const __half* Pg = g_P16 + (size_t)t * BQ * G4;
#pragma unroll
            for (int i = 0; i < 8; i++) {
                int u = i * 256 + tid;
                int row = u >> 4, seg = u & 15;
                cp16(sP + row * SP_STRIDE + seg * 8,
                     Pg + (size_t)(r0 + row) * G4 + n0 + seg * 8);
            }
        }

        float acc[4][4][4];
#pragma unroll
        for (int mt = 0; mt < 4; mt++)
#pragma unroll
            for (int nt = 0; nt < 4; nt++)
#pragma unroll
                for (int q = 0; q < 4; q++) acc[mt][nt][q] = 0.f;

        if (t > 0) {
            const __half* __restrict__ A = Hbuf + (size_t)(t - 1) * BQ * HHD;
            auto load = [&](int kc, int s) {
                __half* sa = sA + s * 16384;
#pragma unroll
                for (int i = 0; i < 8; i++) {
                    int u = i * 256 + tid;
                    int row = u >> 4, seg = u & 15;
                    cp16(sa + row * 128 + ((seg ^ (row & 7)) * 8),
                         A + (size_t)(r0 + row) * HHD + kc * 128 + seg * 8);
                }
                uint32_t* sb = sB + s * 8192;
#pragma unroll
                for (int k16l = 0; k16l < 8; k16l++) {
                    cp16(sb + k16l * 1024 + tid * 4,
                         W + ((size_t)(kc * 8 + k16l) * 256 + n8base) * 64 + tid * 4);
                }
                CPCOMMIT();
            };

            load(0, 0);
            load(1, 1);
            for (int kc = 0; kc < 4; kc++) {
                int s = kc & 1;
                if (kc < 3) CPWAIT(1);
                else        CPWAIT(0);
                __syncthreads();
                const uint32_t sa_u = abase + s * 32768;
                const uint32_t* sb = sB + s * 8192;
#pragma unroll
                for (int k16l = 0; k16l < 8; k16l++) {
                    const uint32_t grp = (uint32_t)(((k16l * 2 + gsel) ^ rr8) * 16);
                    uint32_t a[4][4];
#pragma unroll
                    for (int mt = 0; mt < 4; mt++) ldmat4(a[mt], sa_u + mt * 4096 + grp);
#pragma unroll
                    for (int nt = 0; nt < 4; nt++) {
                        uint2 b = *(const uint2*)(sb + (k16l * 16 + warpN * 4 + nt) * 64 + lane * 2);
#pragma unroll
                        for (int mt = 0; mt < 4; mt++) mma16(acc[mt][nt], a[mt], b.x, b.y);
                    }
                }
                __syncthreads();
                if (kc + 2 < 4) load(kc + 2, s);
            }
        } else {
            CPCOMMIT();
            CPWAIT(0);
            __syncthreads();
        }

        // fused LSTM cell epilogue (P from smem; hw tanh)
        __half* hout = Hbuf + (size_t)t * BQ * HHD;
#pragma unroll
        for (int mt = 0; mt < 4; mt++) {
#pragma unroll
            for (int rr = 0; rr < 2; rr++) {
                int lrow = warpM * 64 + mt * 16 + (lane >> 2) + rr * 8;
                const __half* prow = sP + (size_t)lrow * SP_STRIDE + warpN * 32 + (lane & 3) * 2;
                float2 pi = __half22float2(*(const __half2*)(prow));
                float2 pf = __half22float2(*(const __half2*)(prow + 8));
                float2 pg = __half22float2(*(const __half2*)(prow + 16));
                float2 po = __half22float2(*(const __half2*)(prow + 24));
                float i0 = sigm(acc[mt][0][rr * 2 + 0] + pi.x);
                float i1 = sigm(acc[mt][0][rr * 2 + 1] + pi.y);
                float f0 = sigm(acc[mt][1][rr * 2 + 0] + pf.x);
                float f1 = sigm(acc[mt][1][rr * 2 + 1] + pf.y);
                float gg0 = tnh(acc[mt][2][rr * 2 + 0] + pg.x);
                float gg1 = tnh(acc[mt][2][rr * 2 + 1] + pg.y);
                float o0 = sigm(acc[mt][3][rr * 2 + 0] + po.x);
                float o1 = sigm(acc[mt][3][rr * 2 + 1] + po.y);
                float c0 = f0 * cst[mt][rr][0] + i0 * gg0;
                float c1 = f1 * cst[mt][rr][1] + i1 * gg1;
                cst[mt][rr][0] = c0;
                cst[mt][rr][1] = c1;
                int b = r0 + lrow;
                *(__half2*)&hout[(size_t)b * HHD + j0] =
                    __floats2half2_rn(o0 * tnh(c0), o1 * tnh(c1));
            }
        }
        group_bar(slot, base + t + 1);
    }
}

// ---------------- final FC: fp16 tensor GEMM split-K over t -> fp32 partials ----------------
__global__ void __launch_bounds__(256, 2) fc16() {
    extern __shared__ char smem[];
    __half* sA = (__half*)smem;
    uint32_t* sB = (uint32_t*)(smem + SB_OFF);
    const uint32_t saddr = (uint32_t)__cvta_generic_to_shared(smem);

    const int tid = threadIdx.x, lane = tid & 31, wid = tid >> 5;
    const int warpM = wid >> 2, warpN = wid & 3;
    const int r0 = blockIdx.x * 128;
    const int t = blockIdx.y;
    const __half* __restrict__ A = g_H16[(LL - 1) & 1] + (size_t)t * BQ * HHD;
    const uint32_t* __restrict__ W = g_FcH + (size_t)t * 32768;

    const int quad = lane >> 3, rr8 = lane & 7;
    const int gsel = quad >> 1;
    const uint32_t abase = saddr + (uint32_t)(warpM * 64 + rr8 + (quad & 1) * 8) * 128;

    float acc[4][4][4];
#pragma unroll
    for (int mt = 0; mt < 4; mt++)
#pragma unroll
        for (int nt = 0; nt < 4; nt++)
#pragma unroll
            for (int q = 0; q < 4; q++) acc[mt][nt][q] = 0.f;

    auto load = [&](int kc, int s) {
        __half* sa = sA + s * 8192;
#pragma unroll
        for (int i = 0; i < 4; i++) {
            int u = i * 256 + tid;
            int row = u >> 3, seg = u & 7;
            cp16(sa + row * 64 + (seg ^ (row & 7)) * 8,
                 A + (size_t)(r0 + row) * HHD + kc * 64 + seg * 8);
        }
        uint32_t* sb = sB + s * 4096;
#pragma unroll
        for (int k16l = 0; k16l < 4; k16l++) {
            cp16(sb + k16l * 1024 + tid * 4,
                 W + (size_t)(kc * 4 + k16l) * 1024 + tid * 4);
        }
        CPCOMMIT();
    };

    load(0, 0);
    load(1, 1);
    for (int kc = 0; kc < 8; kc++) {
        int s = kc & 1;
        if (kc < 6) CPWAIT(1);
        else        CPWAIT(0);
        __syncthreads();
        const uint32_t sa_u = abase + s * 16384;
        const uint32_t* sb = sB + s * 4096;
#pragma unroll
        for (int k16l = 0; k16l < 4; k16l++) {
            const uint32_t grp = (uint32_t)(((k16l * 2 + gsel) ^ rr8) * 16);
            uint32_t a[4][4];
#pragma unroll
            for (int mt = 0; mt < 4; mt++) ldmat4(a[mt], sa_u + mt * 2048 + grp);
#pragma unroll
            for (int nt = 0; nt < 4; nt++) {
                uint2 b = *(const uint2*)(sb + (k16l * 16 + warpN * 4 + nt) * 64 + lane * 2);
#pragma unroll
                for (int mt = 0; mt < 4; mt++) mma16(acc[mt][nt], a[mt], b.x, b.y);
            }
        }
        __syncthreads();
        if (kc + 2 < 8) load(kc + 2, s);
    }

    float* pout = g_fcp + (size_t)t * BQ * CC;
#pragma unroll
    for (int nt = 0; nt < 4; nt++) {
        int ncol = warpN * 32 + nt * 8 + (lane & 3) * 2;
#pragma unroll
        for (int mt = 0; mt < 4; mt++) {
            int row = r0 + warpM * 64 + mt * 16 + (lane >> 2);
            *(float2*)&pout[(size_t)row * CC + ncol] = make_float2(acc[mt][nt][0], acc[mt][nt][1]);
            *(float2*)&pout[(size_t)(row + 8) * CC + ncol] = make_float2(acc[mt][nt][2], acc[mt][nt][3]);
        }
    }
}

__global__ void fc_reduce(const float* __restrict__ fc_b, float* __restrict__ out) {
    int i = blockIdx.x * blockDim.x + threadIdx.x;
    if (i >= BQ * CC) return;
    float s = fc_b[i & (CC - 1)];
#pragma unroll 8
    for (int t = 0; t < TT; t++) s += g_fcp[(size_t)t * BQ * CC + i];
    out[i] = s;
}

// ---------------- launch ----------------
extern "C" void kernel_launch(void* const* d_in, const int* in_sizes, int n_in,
                              void* d_out, int out_size) {
    const float* x     = (const float*)d_in[0];
    const float* w_ih0 = (const float*)d_in[1];
    const float* w_hh0 = (const float*)d_in[2];
    const float* b_ih0 = (const float*)d_in[3];
    const float* b_hh0 = (const float*)d_in[4];
    const float* w_ih  = (const float*)d_in[5];
    const float* w_hh  = (const float*)d_in[6];
    const float* b_ih  = (const float*)d_in[7];
    const float* b_hh  = (const float*)d_in[8];
    const float* fc_w  = (const float*)d_in[9];
    const float* fc_b  = (const float*)d_in[10];
    float* out = (float*)d_out;

    cudaFuncSetAttribute(proj16, cudaFuncAttributeMaxDynamicSharedMemorySize, PROJ_SMEM);
    cudaFuncSetAttribute(recur16, cudaFuncAttributeMaxDynamicSharedMemorySize, RECUR_SMEM);
    cudaFuncSetAttribute(fc16, cudaFuncAttributeMaxDynamicSharedMemorySize, PROJ_SMEM);

    prep_x<<<2048, 256>>>(x);
    prep_wi<<<4096, 256>>>(w_ih0, w_ih);
    prep_wr<<<4096, 256>>>(w_hh0, w_hh);
    prep_fcw<<<2048, 256>>>(fc_w);
    prep_bias<<<64, 256>>>(b_ih0, b_hh0, b_ih, b_hh);

    for (int l = 0; l < LL; l++) {
        proj16<<<dim3(16, 512), 256, PROJ_SMEM>>>(l);
        recur16<<<dim3(16, 8), 256, RECUR_SMEM>>>(l);
    }

    fc16<<<dim3(8, TT), 256, PROJ_SMEM>>>();
    fc_reduce<<<(BQ * CC + 255) / 256, 256>>>(fc_b, out);
}

// round 17
// speedup vs baseline: 1.0793x; 1.0262x over previous
#include <cuda_runtime.h>
#include <cuda_fp16.h>
#include <math.h>
#include <stdint.h>

#define BQ 1024
#define TT 64
#define INDIM 64
#define LL 8
#define HHD 512
#define G4 2048
#define CC 128

// ---------------- device scratch ----------------
__device__ __align__(128) __half g_P16[(size_t)TT * BQ * G4];      // gate preactivations fp16, permuted cols
__device__ __align__(128) __half g_H16[2][(size_t)TT * BQ * HHD];  // hidden seq fp16, ping-pong
__device__ __align__(128) __half g_X16[(size_t)TT * BQ * INDIM];   // x as fp16
__device__ __align__(128) uint32_t g_WiH[((size_t)INDIM + (LL - 1) * HHD) * G4 / 2]; // Wi fragments
__device__ __align__(128) uint32_t g_WrH[(size_t)LL * HHD * G4 / 2];                 // Wr fragments
__device__ __align__(128) uint32_t g_FcH[(size_t)TT * HHD * CC / 2];                 // fc_w fragments per t
__device__ float g_bias[LL * G4];
__device__ float g_fcp[(size_t)TT * BQ * CC];  // FC split-K partials
__device__ int g_cnt2[8 * 32];                 // per-row-group barrier counters (128B apart)
__device__ int g_ph2[8 * 32];                  // per-row-group phases (monotonic)

// hardware tanh (sm_75+): 1 MUFU op
__device__ __forceinline__ float tanha(float x) {
    float y;
    asm("tanh.approx.f32 %0, %1;" : "=f"(y) : "f"(x));
    return y;
}
__device__ __forceinline__ float sigm(float x) { return fmaf(0.5f, tanha(0.5f * x), 0.5f); }
__device__ __forceinline__ float tnh(float x) { return tanha(x); }

__device__ __forceinline__ void cp16(void* dst, const void* src) {
    uint32_t d = (uint32_t)__cvta_generic_to_shared(dst);
    asm volatile("cp.async.cg.shared.global [%0], [%1], 16;" ::"r"(d), "l"(src));
}

__device__ __forceinline__ void mma16(float* c, const uint32_t* a, uint32_t b0, uint32_t b1) {
    asm volatile(
        "mma.sync.aligned.m16n8k16.row.col.f32.f16.f16.f32 "
        "{%0,%1,%2,%3}, {%4,%5,%6,%7}, {%8,%9}, {%0,%1,%2,%3};"
        : "+f"(c[0]), "+f"(c[1]), "+f"(c[2]), "+f"(c[3])
        : "r"(a[0]), "r"(a[1]), "r"(a[2]), "r"(a[3]), "r"(b0), "r"(b1));
}

__device__ __forceinline__ void ldmat4(uint32_t* a, uint32_t addr) {
    asm volatile(
        "ldmatrix.sync.aligned.m8n8.x4.shared.b16 {%0,%1,%2,%3}, [%4];"
        : "=r"(a[0]), "=r"(a[1]), "=r"(a[2]), "=r"(a[3]) : "r"(addr));
}

#define CPCOMMIT() asm volatile("cp.async.commit_group;" ::: "memory")
#define CPWAIT(n) asm volatile("cp.async.wait_group %0;" ::"n"(n) : "memory")

// sm_70 memory-model barrier primitives
__device__ __forceinline__ int arrive_acqrel(int* p) {
    int v;
    asm volatile("atom.global.add.acq_rel.gpu.s32 %0, [%1], 1;" : "=r"(v) : "l"(p) : "memory");
    return v;
}
__device__ __forceinline__ void st_release(int* p, int v) {
    asm volatile("st.global.release.gpu.s32 [%0], %1;" ::"l"(p), "r"(v) : "memory");
}
__device__ __forceinline__ int ld_acquire(int* p) {
    int v;
    asm volatile("ld.global.acquire.gpu.s32 %0, [%1];" : "=r"(v) : "l"(p) : "memory");
    return v;
}

// column permutation: n_log(g, j) = (j>>5)*128 + ((j>>3)&3)*32 + g*8 + (j&7)

// ---------------- weight prep: fp16 fragment images ----------------
__global__ void prep_wi(const float* __restrict__ w_ih0, const float* __restrict__ w_ih) {
    const size_t R0 = (size_t)INDIM * G4 / 2;
    size_t total = R0 + (size_t)(LL - 1) * HHD * G4 / 2;
    size_t stride = (size_t)gridDim.x * blockDim.x;
    for (size_t idx = (size_t)blockIdx.x * blockDim.x + threadIdx.x; idx < total; idx += stride) {
        int l;
        uint32_t rem;
        if (idx < R0) { l = 0; rem = (uint32_t)idx; }
        else { size_t r = idx - R0; l = 1 + (int)(r >> 19); rem = (uint32_t)(r & 524287u); }
        int rr = rem & 1, lane = (rem >> 1) & 31, n8 = (rem >> 6) & 255, k16 = rem >> 14;
        int k0 = k16 * 16 + (lane & 3) * 2 + rr * 8;
        int nlog = n8 * 8 + (lane >> 2);
        int j = ((nlog >> 7) << 5) + (((nlog >> 5) & 3) << 3) + (nlog & 7);
        int g = (nlog >> 3) & 3;
        float v0, v1;
        if (l == 0) {
            const float* p = w_ih0 + (size_t)(g * HHD + j) * INDIM + k0;
            v0 = p[0]; v1 = p[1];
        } else {
            const float* p = w_ih + ((size_t)(l - 1) * G4 + g * HHD + j) * HHD + k0;
            v0 = p[0]; v1 = p[1];
        }
        __half2 h = __floats2half2_rn(v0, v1);
        g_WiH[idx] = *(uint32_t*)&h;
    }
}

__global__ void prep_wr(const float* __restrict__ w_hh0, const float* __restrict__ w_hh) {
    size_t total = (size_t)LL * HHD * G4 / 2;
    size_t stride = (size_t)gridDim.x * blockDim.x;
    for (size_t idx = (size_t)blockIdx.x * blockDim.x + threadIdx.x; idx < total; idx += stride) {
        int l = (int)(idx >> 19);
        uint32_t rem = (uint32_t)(idx & 524287u);
        int rr = rem & 1, lane = (rem >> 1) & 31, n8 = (rem >> 6) & 255, k16 = rem >> 14;
        int k0 = k16 * 16 + (lane & 3) * 2 + rr * 8;
        int nlog = n8 * 8 + (lane >> 2);
        int j = ((nlog >> 7) << 5) + (((nlog >> 5) & 3) << 3) + (nlog & 7);
        int g = (nlog >> 3) & 3;
        float v0, v1;
        if (l == 0) {
            const float* p = w_hh0 + (size_t)(g * HHD + j) * HHD + k0;
            v0 = p[0]; v1 = p[1];
        } else {
            const float* p = w_hh + ((size_t)(l - 1) * G4 + g * HHD + j) * HHD + k0;
            v0 = p[0]; v1 = p[1];
        }
        __half2 h = __floats2half2_rn(v0, v1);
        g_WrH[idx] = *(uint32_t*)&h;
    }
}

// fc_w fragments: per t, [k16(32)][c8(16)][lane(32)][2]; value fc_w[c][t*HHD + k]
__global__ void prep_fcw(const float* __restrict__ fw) {
    size_t total = (size_t)TT * HHD * CC / 2;
    size_t stride = (size_t)gridDim.x * blockDim.x;
    for (size_t idx = (size_t)blockIdx.x * blockDim.x + threadIdx.x; idx < total; idx += stride) {
        uint32_t rem = (uint32_t)(idx & 32767u);
        int t = (int)(idx >> 15);
        int rr = rem & 1, lane = (rem >> 1) & 31, c8 = (rem >> 6) & 15, k16 = rem >> 10;
        int k0 = k16 * 16 + (lane & 3) * 2 + rr * 8;
        int c = c8 * 8 + (lane >> 2);
        const float* p = fw + (size_t)c * (TT * HHD) + (size_t)t * HHD + k0;
        __half2 h = __floats2half2_rn(p[0], p[1]);
        g_FcH[idx] = *(uint32_t*)&h;
    }
}

__global__ void prep_bias(const float* __restrict__ b_ih0, const float* __restrict__ b_hh0,
                          const float* __restrict__ b_ih, const float* __restrict__ b_hh) {
    int idx = blockIdx.x * blockDim.x + threadIdx.x;
    if (idx >= LL * G4) return;
    int l = idx >> 11, nlog = idx & 2047;
    int j = ((nlog >> 7) << 5) + (((nlog >> 5) & 3) << 3) + (nlog & 7);
    int g = (nlog >> 3) & 3;
    float v = (l == 0) ? (b_ih0[g * HHD + j] + b_hh0[g * HHD + j])
                       : (b_ih[(l - 1) * G4 + g * HHD + j] + b_hh[(l - 1) * G4 + g * HHD + j]);
    g_bias[idx] = v;
}

__global__ void prep_x(const float* __restrict__ x) {
    size_t total = (size_t)TT * BQ * INDIM;
    size_t stride = (size_t)gridDim.x * blockDim.x;
    for (size_t idx = (size_t)blockIdx.x * blockDim.x + threadIdx.x; idx < total; idx += stride) {
        int k = (int)(idx & 63);
        int r = (int)(idx >> 6);
        int b = r & (BQ - 1), t = r >> 10;
        g_X16[idx] = __float2half(x[((size_t)b * TT + t) * INDIM + k]);
    }
}

// proj/fc smem: sA[2][128*64 halves]=32768, sB[2][4096 u32]=32768
#define SB_OFF 32768
#define PROJ_SMEM 65536
// recur smem (K=128 chunks): sA[2][128*128 halves]=65536, sB[2][8192 u32]=65536 @65536,
// sP 128 x 136-half stride = 34816 @131072
#define RB_OFF 65536
#define RSP_OFF 131072
#define SP_STRIDE 136
#define RECUR_SMEM (RSP_OFF + 128 * SP_STRIDE * 2)

// ---------------- input projection: fp16 tensor GEMM (unchanged) ----------------
__global__ void __launch_bounds__(256, 2) proj16(int layer) {
    extern __shared__ char smem[];
    __half* sA = (__half*)smem;
    uint32_t* sB = (uint32_t*)(smem + SB_OFF);
    const uint32_t saddr = (uint32_t)__cvta_generic_to_shared(smem);

    const int tid = threadIdx.x, lane = tid & 31, wid = tid >> 5;
    const int warpM = wid >> 2, warpN = wid & 3;
    const int n8base = blockIdx.x * 16;
    const int n0 = blockIdx.x * 128;
    const int r0 = blockIdx.y * 128;
    const int K = (layer == 0) ? INDIM : HHD;
    const int NC = K / 64;
    const __half* __restrict__ A = (layer == 0) ? g_X16 : g_H16[(layer - 1) & 1];
    const uint32_t* __restrict__ W =
        g_WiH + ((layer == 0) ? (size_t)0 : (size_t)(INDIM * G4 / 2) + (size_t)(layer - 1) * (HHD * G4 / 2));

    const int quad = lane >> 3, rr8 = lane & 7;
    const int gsel = quad >> 1;
    const uint32_t abase = saddr + (uint32_t)(warpM * 64 + rr8 + (quad & 1) * 8) * 128;

    float acc[4][4][4];
#pragma unroll
    for (int mt = 0; mt < 4; mt++)
#pragma unroll
        for (int nt = 0; nt < 4; nt++)
#pragma unroll
            for (int q = 0; q < 4; q++) acc[mt][nt][q] = 0.f;

    auto load = [&](int kc, int s) {
        __half* sa = sA + s * 8192;
#pragma unroll
        for (int i = 0; i < 4; i++) {
            int u = i * 256 + tid;
            int row = u >> 3, seg = u & 7;
            cp16(sa + row * 64 + (seg ^ (row & 7)) * 8,
                 A + (size_t)(r0 + row) * K + kc * 64 + seg * 8);
        }
        uint32_t* sb = sB + s * 4096;
#pragma unroll
        for (int k16l = 0; k16l < 4; k16l++) {
            cp16(sb + k16l * 1024 + tid * 4,
                 W + ((size_t)(kc * 4 + k16l) * 256 + n8base) * 64 + tid * 4);
        }
        CPCOMMIT();
    };

    load(0, 0);
    if (NC > 1) load(1, 1);
    for (int kc = 0; kc < NC; kc++) {
        int s = kc & 1;
        if (kc + 2 <= NC) CPWAIT(1);
        else              CPWAIT(0);
        __syncthreads();
        const uint32_t sa_u = abase + s * 16384;
        const uint32_t* sb = sB + s * 4096;
#pragma unroll
        for (int k16l = 0; k16l < 4; k16l++) {
            const uint32_t grp = (uint32_t)(((k16l * 2 + gsel) ^ rr8) * 16);
            uint32_t a[4][4];
#pragma unroll
            for (int mt = 0; mt < 4; mt++) ldmat4(a[mt], sa_u + mt * 2048 + grp);
#pragma unroll
            for (int nt = 0; nt < 4; nt++) {
                uint2 b = *(const uint2*)(sb + (k16l * 16 + warpN * 4 + nt) * 64 + lane * 2);
#pragma unroll
                for (int mt = 0; mt < 4; mt++) mma16(acc[mt][nt], a[mt], b.x, b.y);
            }
        }
        __syncthreads();
        if (kc + 2 < NC) load(kc + 2, s);
    }

    const float* __restrict__ bias = g_bias + layer * G4;
#pragma unroll
    for (int nt = 0; nt < 4; nt++) {
        int ncol = n0 + warpN * 32 + nt * 8 + (lane & 3) * 2;
        float2 bv = *(const float2*)&bias[ncol];
#pragma unroll
        for (int mt = 0; mt < 4; mt++) {
            int row = r0 + warpM * 64 + mt * 16 + (lane >> 2);
            *(__half2*)&g_P16[(size_t)row * G4 + ncol] =
                __floats2half2_rn(acc[mt][nt][0] + bv.x, acc[mt][nt][1] + bv.y);
            *(__half2*)&g_P16[(size_t)(row + 8) * G4 + ncol] =
                __floats2half2_rn(acc[mt][nt][2] + bv.x, acc[mt][nt][3] + bv.y);
        }
    }
}

// ---------------- per-row-group barrier (acq_rel atomics, spin wait) ----------------
__device__ __forceinline__ void group_bar(int slot, int target) {
    __syncthreads();
    if (threadIdx.x == 0) {
        int v = arrive_acqrel(&g_cnt2[slot]);  // releases this block's h-stores; leader acquires all
        if (v == 15) {
            g_cnt2[slot] = 0;                  // ordered before phase publication by release below
            st_release(&g_ph2[slot], target);
        } else {
            while (ld_acquire(&g_ph2[slot]) < target) { }
        }
    }
    __syncthreads();
}

// ---------------- persistent recurrent layer: K=128 chunks, split barriers ----------------
__global__ void __launch_bounds__(256, 1) recur16(int layer) {
    extern __shared__ char smem[];
    __half* sA = (__half*)smem;                   // 2 x 16384 halves (row stride 128)
    uint32_t* sB = (uint32_t*)(smem + RB_OFF);    // 2 x 8192 u32
    __half* sP = (__half*)(smem + RSP_OFF);
    const uint32_t saddr = (uint32_t)__cvta_generic_to_shared(smem);

    const int tid = threadIdx.x, lane = tid & 31, wid = tid >> 5;
    const int warpM = wid >> 2, warpN = wid & 3;
    const int n8base = blockIdx.x * 16;
    const int n0 = blockIdx.x * 128;
    const int r0 = blockIdx.y * 128;
    const int slot = blockIdx.y * 32;

    __half* Hbuf = g_H16[layer & 1];
    const uint32_t* __restrict__ W = g_WrH + (size_t)layer * (HHD * G4 / 2);
    const int base = ld_acquire(&g_ph2[slot]);

    const int quad = lane >> 3, rr8 = lane & 7;
    const int gsel = quad >> 1;
    const uint32_t abase = saddr + (uint32_t)(warpM * 64 + rr8 + (quad & 1) * 8) * 256;

    float cst[4][2][2];
#pragma unroll
    for (int mt = 0; mt < 4; mt++)
#pragma unroll
        for (int rr = 0; rr < 2; rr++) { cst[mt][rr][0] = 0.f; cst[mt][rr][1] = 0.f; }

    const int j0 = blockIdx.x * 32 + warpN * 8 + (lane & 3) * 2;

    for (int t = 0; t < TT; t++) {
        // prefetch P tile into smem (joins first commit group of this step)
        {
            const __half* Pg = g_P16 + (size_t)t * BQ * G4;
#pragma unroll
            for (int i = 0; i < 8; i++) {
                int u = i * 256 + tid;
                int row = u >> 4, seg = u & 15;
                cp16(sP + row * SP_STRIDE + seg * 8,
                     Pg + (size_t)(r0 + row) * G4 + n0 + seg * 8);
            }
        }

        float acc[4][4][4];
#pragma unroll
        for (int mt = 0; mt < 4; mt++)
#pragma unroll
            for (int nt = 0; nt < 4; nt++)
#pragma unroll
                for (int q = 0; q < 4; q++) acc[mt][nt][q] = 0.f;

        if (t > 0) {
            const __half* __restrict__ A = Hbuf + (size_t)(t - 1) * BQ * HHD;
            auto load = [&](int kc, int s) {
                __half* sa = sA + s * 16384;
#pragma unroll
                for (int i = 0; i < 8; i++) {
                    int u = i * 256 + tid;
                    int row = u >> 4, seg = u & 15;
                    cp16(sa + row * 128 + ((seg ^ (row & 7)) * 8),
                         A + (size_t)(r0 + row) * HHD + kc * 128 + seg * 8);
                }
                uint32_t* sb = sB + s * 8192;
#pragma unroll
                for (int k16l = 0; k16l < 8; k16l++) {
                    cp16(sb + k16l * 1024 + tid * 4,
                         W + ((size_t)(kc * 8 + k16l) * 256 + n8base) * 64 + tid * 4);
                }
                CPCOMMIT();
            };

            load(0, 0);
            load(1, 1);
            for (int kc = 0; kc < 4; kc++) {
                int s = kc & 1;
                if (kc < 3) CPWAIT(1);
                else        CPWAIT(0);
                __syncthreads();
                const uint32_t sa_u = abase + s * 32768;
                const uint32_t* sb = sB + s * 8192;
#pragma unroll
                for (int k16l = 0; k16l < 8; k16l++) {
                    const uint32_t grp = (uint32_t)(((k16l * 2 + gsel) ^ rr8) * 16);
                    uint32_t a[4][4];
#pragma unroll
                    for (int mt = 0; mt < 4; mt++) ldmat4(a[mt], sa_u + mt * 4096 + grp);
#pragma unroll
                    for (int nt = 0; nt < 4; nt++) {
                        uint2 b = *(const uint2*)(sb + (k16l * 16 + warpN * 4 + nt) * 64 + lane * 2);
#pragma unroll
                        for (int mt = 0; mt < 4; mt++) mma16(acc[mt][nt], a[mt], b.x, b.y);
                    }
                }
                __syncthreads();
                if (kc + 2 < 4) load(kc + 2, s);
            }
        } else {
            CPCOMMIT();
            CPWAIT(0);
            __syncthreads();
        }

        // fused LSTM cell epilogue (P from smem; hw tanh)
        __half* hout = Hbuf + (size_t)t * BQ * HHD;
#pragma unroll
        for (int mt = 0; mt < 4; mt++) {
#pragma unroll
            for (int rr = 0; rr < 2; rr++) {
                int lrow = warpM * 64 + mt * 16 + (lane >> 2) + rr * 8;
                const __half* prow = sP + (size_t)lrow * SP_STRIDE + warpN * 32 + (lane & 3) * 2;
                float2 pi = __half22float2(*(const __half2*)(prow));
                float2 pf = __half22float2(*(const __half2*)(prow + 8));
                float2 pg = __half22float2(*(const __half2*)(prow + 16));
                float2 po = __half22float2(*(const __half2*)(prow + 24));
                float i0 = sigm(acc[mt][0][rr * 2 + 0] + pi.x);
                float i1 = sigm(acc[mt][0][rr * 2 + 1] + pi.y);
                float f0 = sigm(acc[mt][1][rr * 2 + 0] + pf.x);
                float f1 = sigm(acc[mt][1][rr * 2 + 1] + pf.y);
                float gg0 = tnh(acc[mt][2][rr * 2 + 0] + pg.x);
                float gg1 = tnh(acc[mt][2][rr * 2 + 1] + pg.y);
                float o0 = sigm(acc[mt][3][rr * 2 + 0] + po.x);
                float o1 = sigm(acc[mt][3][rr * 2 + 1] + po.y);
                float c0 = f0 * cst[mt][rr][0] + i0 * gg0;
                float c1 = f1 * cst[mt][rr][1] + i1 * gg1;
                cst[mt][rr][0] = c0;
                cst[mt][rr][1] = c1;
                int b = r0 + lrow;
                *(__half2*)&hout[(size_t)b * HHD + j0] =
                    __floats2half2_rn(o0 * tnh(c0), o1 * tnh(c1));
            }
        }
        group_bar(slot, base + t + 1);
    }
}

// ---------------- final FC: fp16 tensor GEMM split-K over t -> fp32 partials ----------------
__global__ void __launch_bounds__(256, 2) fc16() {
    extern __shared__ char smem[];
    __half* sA = (__half*)smem;
    uint32_t* sB = (uint32_t*)(smem + SB_OFF);
    const uint32_t saddr = (uint32_t)__cvta_generic_to_shared(smem);

    const int tid = threadIdx.x, lane = tid & 31, wid = tid >> 5;
    const int warpM = wid >> 2, warpN = wid & 3;
    const int r0 = blockIdx.x * 128;
    const int t = blockIdx.y;
    const __half* __restrict__ A = g_H16[(LL - 1) & 1] + (size_t)t * BQ * HHD;
    const uint32_t* __restrict__ W = g_FcH + (size_t)t * 32768;

    const int quad = lane >> 3, rr8 = lane & 7;
    const int gsel = quad >> 1;
    const uint32_t abase = saddr + (uint32_t)(warpM * 64 + rr8 + (quad & 1) * 8) * 128;

    float acc[4][4][4];
#pragma unroll
    for (int mt = 0; mt < 4; mt++)
#pragma unroll
        for (int nt = 0; nt < 4; nt++)
#pragma unroll
            for (int q = 0; q < 4; q++) acc[mt][nt][q] = 0.f;

    auto load = [&](int kc, int s) {
        __half* sa = sA + s * 8192;
#pragma unroll
        for (int i = 0; i < 4; i++) {
            int u = i * 256 + tid;
            int row = u >> 3, seg = u & 7;
            cp16(sa + row * 64 + (seg ^ (row & 7)) * 8,
                 A + (size_t)(r0 + row) * HHD + kc * 64 + seg * 8);
        }
        uint32_t* sb = sB + s * 4096;
#pragma unroll
        for (int k16l = 0; k16l < 4; k16l++) {
            cp16(sb + k16l * 1024 + tid * 4,
                 W + (size_t)(kc * 4 + k16l) * 1024 + tid * 4);
        }
        CPCOMMIT();
    };

    load(0, 0);
    load(1, 1);
    for (int kc = 0; kc < 8; kc++) {
        int s = kc & 1;
        if (kc < 6) CPWAIT(1);
        else        CPWAIT(0);
        __syncthreads();
        const uint32_t sa_u = abase + s * 16384;
        const uint32_t* sb = sB + s * 4096;
#pragma unroll
        for (int k16l = 0; k16l < 4; k16l++) {
            const uint32_t grp = (uint32_t)(((k16l * 2 + gsel) ^ rr8) * 16);
            uint32_t a[4][4];
#pragma unroll
            for (int mt = 0; mt < 4; mt++) ldmat4(a[mt], sa_u + mt * 2048 + grp);
#pragma unroll
            for (int nt = 0; nt < 4; nt++) {
                uint2 b = *(const uint2*)(sb + (k16l * 16 + warpN * 4 + nt) * 64 + lane * 2);
#pragma unroll
                for (int mt = 0; mt < 4; mt++) mma16(acc[mt][nt], a[mt], b.x, b.y);
            }
        }
        __syncthreads();
        if (kc + 2 < 8) load(kc + 2, s);
    }

    float* pout = g_fcp + (size_t)t * BQ * CC;
#pragma unroll
    for (int nt = 0; nt < 4; nt++) {
        int ncol = warpN * 32 + nt * 8 + (lane & 3) * 2;
#pragma unroll
        for (int mt = 0; mt < 4; mt++) {
            int row = r0 + warpM * 64 + mt * 16 + (lane >> 2);
            *(float2*)&pout[(size_t)row * CC + ncol] = make_float2(acc[mt][nt][0], acc[mt][nt][1]);
            *(float2*)&pout[(size_t)(row + 8) * CC + ncol] = make_float2(acc[mt][nt][2], acc[mt][nt][3]);
        }
    }
}

__global__ void fc_reduce(const float* __restrict__ fc_b, float* __restrict__ out) {
    int i = blockIdx.x * blockDim.x + threadIdx.x;
    if (i >= BQ * CC) return;
    float s = fc_b[i & (CC - 1)];
#pragma unroll 8
    for (int t = 0; t < TT; t++) s += g_fcp[(size_t)t * BQ * CC + i];
    out[i] = s;
}

// ---------------- launch ----------------
extern "C" void kernel_launch(void* const* d_in, const int* in_sizes, int n_in,
                              void* d_out, int out_size) {
    const float* x     = (const float*)d_in[0];
    const float* w_ih0 = (const float*)d_in[1];
    const float* w_hh0 = (const float*)d_in[2];
    const float* b_ih0 = (const float*)d_in[3];
    const float* b_hh0 = (const float*)d_in[4];
    const float* w_ih  = (const float*)d_in[5];
    const float* w_hh  = (const float*)d_in[6];
    const float* b_ih  = (const float*)d_in[7];
    const float* b_hh  = (const float*)d_in[8];
    const float* fc_w  = (const float*)d_in[9];
    const float* fc_b  = (const float*)d_in[10];
    float* out = (float*)d_out;

    cudaFuncSetAttribute(proj16, cudaFuncAttributeMaxDynamicSharedMemorySize, PROJ_SMEM);
    cudaFuncSetAttribute(recur16, cudaFuncAttributeMaxDynamicSharedMemorySize, RECUR_SMEM);
    cudaFuncSetAttribute(fc16, cudaFuncAttributeMaxDynamicSharedMemorySize, PROJ_SMEM);

    prep_x<<<2048, 256>>>(x);
    prep_wi<<<4096, 256>>>(w_ih0, w_ih);
    prep_wr<<<4096, 256>>>(w_hh0, w_hh);
    prep_fcw<<<2048, 256>>>(fc_w);
    prep_bias<<<64, 256>>>(b_ih0, b_hh0, b_ih, b_hh);

    for (int l = 0; l < LL; l++) {
        proj16<<<dim3(16, 512), 256, PROJ_SMEM>>>(l);
        recur16<<<dim3(16, 8), 256, RECUR_SMEM>>>(l);
    }

    fc16<<<dim3(8, TT), 256, PROJ_SMEM>>>();
    fc_reduce<<<(BQ * CC + 255) / 256, 256>>>(fc_b, out);
}